// round 1
// baseline (speedup 1.0000x reference)
#include <cuda_runtime.h>
#include <math.h>
#include <stdint.h>

// ---------------- problem constants ----------------
#define BATCH 8
#define SEQ   96
#define PRED  96
#define NVARS 862
#define NMARK 4
#define LTOK  866            // NVARS + NMARK tokens per batch
#define TTOK  (BATCH*LTOK)   // 6928 total rows
#define DM    512
#define DS    16
#define DFF   512
#define RK    32
#define NL    2

#define CDIV(a,b) (((a)+(b)-1)/(b))

// ---------------- scratch pool (static device memory; no allocs) ----------
// offsets in floats
constexpr size_t OFF_TOK  = 0;                                  // [TTOK,96]
constexpr size_t OFF_DEC  = OFF_TOK  + (size_t)TTOK*96;         // [TTOK,96]
constexpr size_t OFF_ENC  = OFF_DEC  + (size_t)TTOK*96;         // [TTOK,512]
constexpr size_t OFF_RAW  = OFF_ENC  + (size_t)TTOK*DM;
constexpr size_t OFF_XZ0  = OFF_RAW  + (size_t)TTOK*DM;         // [TTOK,1024]
constexpr size_t OFF_XZ1  = OFF_XZ0  + (size_t)TTOK*2*DM;
constexpr size_t OFF_XC0  = OFF_XZ1  + (size_t)TTOK*2*DM;       // [TTOK,512]
constexpr size_t OFF_XC1  = OFF_XC0  + (size_t)TTOK*DM;
constexpr size_t OFF_DBL0 = OFF_XC1  + (size_t)TTOK*DM;         // [TTOK,64]
constexpr size_t OFF_DBL1 = OFF_DBL0 + (size_t)TTOK*64;
constexpr size_t OFF_DLT0 = OFF_DBL1 + (size_t)TTOK*64;         // [TTOK,512]
constexpr size_t OFF_DLT1 = OFF_DLT0 + (size_t)TTOK*DM;
constexpr size_t OFF_YP0  = OFF_DLT1 + (size_t)TTOK*DM;
constexpr size_t OFF_YP1  = OFF_YP0  + (size_t)TTOK*DM;
constexpr size_t OFF_MO0  = OFF_YP1  + (size_t)TTOK*DM;
constexpr size_t OFF_MO1  = OFF_MO0  + (size_t)TTOK*DM;
constexpr size_t OFF_T1   = OFF_MO1  + (size_t)TTOK*DM;
constexpr size_t OFF_T2   = OFF_T1   + (size_t)TTOK*DM;
constexpr size_t OFF_T3   = OFF_T2   + (size_t)TTOK*DM;
constexpr size_t OFF_MEAN = OFF_T3   + (size_t)TTOK*DM;         // [B,NVARS]
constexpr size_t OFF_STD  = OFF_MEAN + (size_t)BATCH*NVARS;
constexpr size_t SCRATCH_FLOATS = OFF_STD + (size_t)BATCH*NVARS;

__device__ float g_scratch[SCRATCH_FLOATS];

// ---------------- GEMM: C[M,N] = act(A[M,K(lda)] * W[N,K]^T + bias) ------
enum { ACT_NONE = 0, ACT_RELU = 1, ACT_SOFTPLUS = 2, ACT_GATE = 3 };

template <int ACT>
__global__ void __launch_bounds__(128)
gemm_kernel(const float* __restrict__ A, int lda,
            const float* __restrict__ W,
            const float* __restrict__ bias,
            float* __restrict__ C,
            int M, int N, int K,
            const float* __restrict__ e1,   // ACT_GATE: ln(enc)
            const float* __restrict__ e2)   // ACT_GATE: raw
{
    __shared__ float As[16][68];
    __shared__ float Bs[16][68];

    const int tid = threadIdx.x;       // 128 threads
    const int tx  = tid & 15;          // column group (4 cols each)
    const int ty  = tid >> 4;          // row group (8 rows each)
    const int bm  = blockIdx.y * 64;
    const int bn  = blockIdx.x * 64;

    float acc[8][4];
#pragma unroll
    for (int i = 0; i < 8; i++)
#pragma unroll
        for (int j = 0; j < 4; j++) acc[i][j] = 0.f;

    const int lc  = tid & 15;          // k within tile for loads
    const int lr0 = tid >> 4;          // base row for loads

    for (int k0 = 0; k0 < K; k0 += 16) {
#pragma unroll
        for (int i = 0; i < 8; i++) {
            int r = lr0 + i * 8;
            int gr = bm + r;
            As[lc][r] = (gr < M) ? A[(size_t)gr * lda + k0 + lc] : 0.f;
        }
#pragma unroll
        for (int i = 0; i < 8; i++) {
            int n = lr0 + i * 8;
            int gn = bn + n;
            Bs[lc][n] = (gn < N) ? W[(size_t)gn * K + k0 + lc] : 0.f;
        }
        __syncthreads();

#pragma unroll
        for (int k = 0; k < 16; k++) {
            float4 b4 = *reinterpret_cast<const float4*>(&Bs[k][tx * 4]);
            float4 a0 = *reinterpret_cast<const float4*>(&As[k][ty * 8]);
            float4 a1 = *reinterpret_cast<const float4*>(&As[k][ty * 8 + 4]);
            float av[8] = {a0.x, a0.y, a0.z, a0.w, a1.x, a1.y, a1.z, a1.w};
            float bv[4] = {b4.x, b4.y, b4.z, b4.w};
#pragma unroll
            for (int i = 0; i < 8; i++)
#pragma unroll
                for (int j = 0; j < 4; j++)
                    acc[i][j] = fmaf(av[i], bv[j], acc[i][j]);
        }
        __syncthreads();
    }

#pragma unroll
    for (int i = 0; i < 8; i++) {
        int gr = bm + ty * 8 + i;
        if (gr >= M) continue;
#pragma unroll
        for (int j = 0; j < 4; j++) {
            int gc = bn + tx * 4 + j;
            if (gc >= N) continue;
            float v = acc[i][j];
            if (bias) v += bias[gc];
            if (ACT == ACT_RELU) {
                v = fmaxf(v, 0.f);
            } else if (ACT == ACT_SOFTPLUS) {
                v = fmaxf(v, 0.f) + log1pf(__expf(-fabsf(v)));
            } else if (ACT == ACT_GATE) {
                float sig = 1.f / (1.f + __expf(-v));
                size_t idx = (size_t)gr * N + gc;
                v = e1[idx] + sig * e2[idx];
            }
            C[(size_t)gr * N + gc] = v;
        }
    }
}

// ---------------- per-(b,n) mean/std over SEQ ----------------------------
__global__ void stats_kernel(const float* __restrict__ x_enc,
                             float* __restrict__ means, float* __restrict__ stds)
{
    int idx = blockIdx.x * blockDim.x + threadIdx.x;
    if (idx >= BATCH * NVARS) return;
    int b = idx / NVARS, n = idx - b * NVARS;
    float s = 0.f, sq = 0.f;
    for (int t = 0; t < SEQ; t++) {
        float v = x_enc[((size_t)b * SEQ + t) * NVARS + n];
        s += v; sq += v * v;
    }
    float m = s * (1.f / SEQ);
    float var = sq * (1.f / SEQ) - m * m;
    means[idx] = m;
    stds[idx] = sqrtf(var + 1e-5f);
}

// ---------------- build tokens: [TTOK, SEQ] ------------------------------
__global__ void tok_kernel(const float* __restrict__ x_enc,
                           const float* __restrict__ x_mark,
                           const float* __restrict__ means,
                           const float* __restrict__ stds,
                           float* __restrict__ tok)
{
    int idx = blockIdx.x * blockDim.x + threadIdx.x;
    if (idx >= TTOK * SEQ) return;
    int sIdx = idx % SEQ;
    int t = idx / SEQ;
    int b = t / LTOK, v = t - b * LTOK;
    float val;
    if (v < NVARS) {
        val = (x_enc[((size_t)b * SEQ + sIdx) * NVARS + v] - means[b * NVARS + v])
              / stds[b * NVARS + v];
    } else {
        val = x_mark[((size_t)b * SEQ + sIdx) * NMARK + (v - NVARS)];
    }
    tok[idx] = val;
}

// ---------------- depthwise conv(2) + SiLU -------------------------------
// fwd (dir=0): xc[l] = silu(cw0*xi[l-1] + cw1*xi[l] + cb)
// rev (dir=1): xc[l] = silu(cw0*xi[l+1] + cw1*xi[l] + cb)
__global__ void conv_silu_kernel(const float* __restrict__ xz,
                                 const float* __restrict__ cw,
                                 const float* __restrict__ cb,
                                 float* __restrict__ xc, int dir)
{
    int idx = blockIdx.x * blockDim.x + threadIdx.x;
    if (idx >= TTOK * DM) return;
    int d = idx & (DM - 1);
    int t = idx >> 9;
    int b = t / LTOK, l = t - b * LTOK;
    float cur = xz[(size_t)t * (2 * DM) + d];
    int ln = dir ? (l + 1) : (l - 1);
    float nb = 0.f;
    if (ln >= 0 && ln < LTOK)
        nb = xz[(size_t)(t + (dir ? 1 : -1)) * (2 * DM) + d];
    float v = cw[d * 2 + 0] * nb + cw[d * 2 + 1] * cur + cb[d];
    xc[idx] = v / (1.f + __expf(-v));  // silu
}

// ---------------- selective scan ------------------------------------------
// one 16-lane group per (b,d) channel; lane = state index s.
// h_t = exp(delta*A[d,s]) * h_{t-1} + delta*B_t[s]*xc ;  y_t = sum_s h*C_t[s]
// ypre = (y + D[d]*xc) * silu(z)
__global__ void __launch_bounds__(256)
scan_kernel(const float* __restrict__ delta,
            const float* __restrict__ xc,
            const float* __restrict__ dbl,   // [T,64]: dt(32) B(16) C(16)
            const float* __restrict__ xz,    // z at column DM..2DM-1
            const float* __restrict__ A_log, // [DM,DS]
            const float* __restrict__ Dp,    // [DM]
            float* __restrict__ ypre, int dir)
{
    int gid = blockIdx.x * (blockDim.x >> 4) + (threadIdx.x >> 4);
    int s = threadIdx.x & 15;
    int b = gid >> 9;          // / DM
    int d = gid & (DM - 1);
    float a = -__expf(A_log[d * DS + s]);
    float Dv = Dp[d];
    float h = 0.f;
    size_t base = (size_t)b * LTOK;
    for (int i = 0; i < LTOK; i++) {
        int l = dir ? (LTOK - 1 - i) : i;
        size_t t = base + l;
        float dlt = delta[t * DM + d];
        float x   = xc[t * DM + d];
        float bm  = dbl[t * 64 + RK + s];
        float cm  = dbl[t * 64 + RK + DS + s];
        float dA = __expf(dlt * a);
        h = dA * h + (dlt * bm) * x;
        float p = h * cm;
        p += __shfl_xor_sync(0xffffffffu, p, 1);
        p += __shfl_xor_sync(0xffffffffu, p, 2);
        p += __shfl_xor_sync(0xffffffffu, p, 4);
        p += __shfl_xor_sync(0xffffffffu, p, 8);
        if (s == 0) {
            float z = xz[t * (2 * DM) + DM + d];
            float sz = z / (1.f + __expf(-z));
            ypre[t * DM + d] = (p + Dv * x) * sz;
        }
    }
}

// ---------------- LayerNorm over DM with up to 3 summed inputs ----------
__global__ void ln_kernel(const float* __restrict__ i1,
                          const float* __restrict__ i2,
                          const float* __restrict__ i3,
                          const float* __restrict__ g,
                          const float* __restrict__ bta,
                          float* __restrict__ out)
{
    int row = blockIdx.x * (blockDim.x >> 5) + (threadIdx.x >> 5);
    int lane = threadIdx.x & 31;
    if (row >= TTOK) return;
    size_t rb = (size_t)row * DM;
    float vals[16];
    float s = 0.f, sq = 0.f;
#pragma unroll
    for (int i = 0; i < 16; i++) {
        int c = lane + i * 32;
        float v = i1[rb + c];
        if (i2) v += i2[rb + c];
        if (i3) v += i3[rb + c];
        vals[i] = v; s += v; sq += v * v;
    }
#pragma unroll
    for (int o = 16; o; o >>= 1) {
        s  += __shfl_xor_sync(0xffffffffu, s, o);
        sq += __shfl_xor_sync(0xffffffffu, sq, o);
    }
    float m = s * (1.f / DM);
    float var = sq * (1.f / DM) - m * m;
    float r = rsqrtf(var + 1e-5f);
#pragma unroll
    for (int i = 0; i < 16; i++) {
        int c = lane + i * 32;
        out[rb + c] = (vals[i] - m) * r * g[c] + bta[c];
    }
}

// ---------------- final transpose + de-normalization ---------------------
// out[b,p,n] = dec[(b*LTOK+n)*PRED + p] * std[b,n] + mean[b,n]
__global__ void out_kernel(const float* __restrict__ dec,
                           const float* __restrict__ means,
                           const float* __restrict__ stds,
                           float* __restrict__ out)
{
    int idx = blockIdx.x * blockDim.x + threadIdx.x;
    if (idx >= BATCH * PRED * NVARS) return;
    int b = idx / (PRED * NVARS);
    int rem = idx - b * (PRED * NVARS);
    int p = rem / NVARS;
    int n = rem - p * NVARS;
    float v = dec[((size_t)b * LTOK + n) * PRED + p];
    out[idx] = v * stds[b * NVARS + n] + means[b * NVARS + n];
}

// ---------------- host orchestration -------------------------------------
template <int ACT>
static void launch_gemm(const float* A, int lda, const float* W, const float* bias,
                        float* C, int M, int N, int K,
                        const float* e1 = nullptr, const float* e2 = nullptr)
{
    dim3 grid(CDIV(N, 64), CDIV(M, 64));
    gemm_kernel<ACT><<<grid, 128>>>(A, lda, W, bias, C, M, N, K, e1, e2);
}

extern "C" void kernel_launch(void* const* d_in, const int* in_sizes, int n_in,
                              void* d_out, int out_size)
{
    const float* x_enc    = (const float*)d_in[0];
    const float* x_mark   = (const float*)d_in[1];
    // d_in[2], d_in[3] (x_dec, x_mark_dec) unused by reference
    const float* emb_w    = (const float*)d_in[4];   // [DM,SEQ]
    const float* emb_b    = (const float*)d_in[5];
    const float* in_proj  = (const float*)d_in[6];   // [NL,2,2DM,DM]
    const float* conv_w   = (const float*)d_in[7];   // [NL,2,DM,2]
    const float* conv_b   = (const float*)d_in[8];   // [NL,2,DM]
    const float* x_proj   = (const float*)d_in[9];   // [NL,2,64,DM]
    const float* dt_w     = (const float*)d_in[10];  // [NL,2,DM,RK]
    const float* dt_b     = (const float*)d_in[11];  // [NL,2,DM]
    const float* A_log    = (const float*)d_in[12];  // [NL,2,DM,DS]
    const float* D_param  = (const float*)d_in[13];  // [NL,2,DM]
    const float* out_w    = (const float*)d_in[14];  // [NL,2,DM,DM]
    const float* ffn_w1   = (const float*)d_in[15];  // [NL,DFF,DM]
    const float* ffn_b1   = (const float*)d_in[16];
    const float* ffn_w2   = (const float*)d_in[17];  // [NL,DM,DFF]
    const float* ffn_b2   = (const float*)d_in[18];
    const float* ln1_g    = (const float*)d_in[19];
    const float* ln1_b    = (const float*)d_in[20];
    const float* ln2_g    = (const float*)d_in[21];
    const float* ln2_b    = (const float*)d_in[22];
    const float* fin_g    = (const float*)d_in[23];
    const float* fin_b    = (const float*)d_in[24];
    const float* gate_w   = (const float*)d_in[25];  // [DM,DM]
    const float* gate_b   = (const float*)d_in[26];
    const float* proj_w   = (const float*)d_in[27];  // [PRED,DM]
    const float* proj_b   = (const float*)d_in[28];

    float* S = nullptr;
    cudaGetSymbolAddress((void**)&S, g_scratch);

    float* tok   = S + OFF_TOK;
    float* dec   = S + OFF_DEC;
    float* enc   = S + OFF_ENC;
    float* raw   = S + OFF_RAW;
    float* xz[2]  = { S + OFF_XZ0,  S + OFF_XZ1 };
    float* xcb[2] = { S + OFF_XC0,  S + OFF_XC1 };
    float* dbl[2] = { S + OFF_DBL0, S + OFF_DBL1 };
    float* dlt[2] = { S + OFF_DLT0, S + OFF_DLT1 };
    float* yp[2]  = { S + OFF_YP0,  S + OFF_YP1 };
    float* mo[2]  = { S + OFF_MO0,  S + OFF_MO1 };
    float* t1    = S + OFF_T1;
    float* t2    = S + OFF_T2;
    float* t3    = S + OFF_T3;
    float* means = S + OFF_MEAN;
    float* stds  = S + OFF_STD;

    // 1) instance-norm statistics
    stats_kernel<<<CDIV(BATCH * NVARS, 256), 256>>>(x_enc, means, stds);

    // 2) tokens [TTOK, SEQ]
    tok_kernel<<<CDIV(TTOK * SEQ, 256), 256>>>(x_enc, x_mark, means, stds, tok);

    // 3) embedding GEMM -> enc [TTOK, DM]
    launch_gemm<ACT_NONE>(tok, SEQ, emb_w, emb_b, enc, TTOK, DM, SEQ);

    // raw = enc
    cudaMemcpyAsync(raw, enc, (size_t)TTOK * DM * sizeof(float),
                    cudaMemcpyDeviceToDevice);

    for (int l = 0; l < NL; l++) {
        for (int dir = 0; dir < 2; dir++) {
            int w = l * 2 + dir;
            // in_proj: [TTOK,2DM]
            launch_gemm<ACT_NONE>(enc, DM, in_proj + (size_t)w * 2 * DM * DM,
                                  nullptr, xz[dir], TTOK, 2 * DM, DM);
            // conv + silu -> xc
            conv_silu_kernel<<<CDIV(TTOK * DM, 256), 256>>>(
                xz[dir], conv_w + (size_t)w * DM * 2, conv_b + (size_t)w * DM,
                xcb[dir], dir);
            // x_proj: [TTOK,64]
            launch_gemm<ACT_NONE>(xcb[dir], DM, x_proj + (size_t)w * 64 * DM,
                                  nullptr, dbl[dir], TTOK, 64, DM);
            // delta = softplus(dt @ dt_w^T + dt_b): [TTOK,DM]
            launch_gemm<ACT_SOFTPLUS>(dbl[dir], 64, dt_w + (size_t)w * DM * RK,
                                      dt_b + (size_t)w * DM, dlt[dir],
                                      TTOK, DM, RK);
            // selective scan -> ypre
            scan_kernel<<<(BATCH * DM * 16) / 256, 256>>>(
                dlt[dir], xcb[dir], dbl[dir], xz[dir],
                A_log + (size_t)w * DM * DS, D_param + (size_t)w * DM,
                yp[dir], dir);
            // out proj
            launch_gemm<ACT_NONE>(yp[dir], DM, out_w + (size_t)w * DM * DM,
                                  nullptr, mo[dir], TTOK, DM, DM);
        }
        // x = LN(enc + fwd + rev)
        ln_kernel<<<CDIV(TTOK, 8), 256>>>(enc, mo[0], mo[1],
                                          ln1_g + l * DM, ln1_b + l * DM, t1);
        // FFN
        launch_gemm<ACT_RELU>(t1, DM, ffn_w1 + (size_t)l * DFF * DM,
                              ffn_b1 + l * DFF, t2, TTOK, DFF, DM);
        launch_gemm<ACT_NONE>(t2, DFF, ffn_w2 + (size_t)l * DM * DFF,
                              ffn_b2 + l * DM, t3, TTOK, DM, DFF);
        // enc = LN(x + y)
        ln_kernel<<<CDIV(TTOK, 8), 256>>>(t1, t3, nullptr,
                                          ln2_g + l * DM, ln2_b + l * DM, enc);
    }

    // final LN -> t2
    ln_kernel<<<CDIV(TTOK, 8), 256>>>(enc, nullptr, nullptr, fin_g, fin_b, t2);

    // gated residual: t1 = t2 + sigmoid(raw@gate_w^T + gate_b) * raw
    launch_gemm<ACT_GATE>(raw, DM, gate_w, gate_b, t1, TTOK, DM, DM, t2, raw);

    // projection to PRED -> dec [TTOK, 96]
    launch_gemm<ACT_NONE>(t1, DM, proj_w, proj_b, dec, TTOK, PRED, DM);

    // transpose + de-normalize
    out_kernel<<<CDIV(BATCH * PRED * NVARS, 256), 256>>>(dec, means, stds,
                                                         (float*)d_out);
}

// round 3
// speedup vs baseline: 1.2294x; 1.2294x over previous
#include <cuda_runtime.h>
#include <cuda_bf16.h>
#include <math.h>
#include <stdint.h>

// ---------------- problem constants ----------------
#define BATCH 8
#define SEQ   96
#define PRED  96
#define NVARS 862
#define NMARK 4
#define LTOK  866
#define TTOK  (BATCH*LTOK)   // 6928
#define DM    512
#define DS    16
#define DFF   512
#define RK    32
#define NL    2

#define CDIV(a,b) (((a)+(b)-1)/(b))

// ================= scratch (static; no allocs) =============================
constexpr size_t OFF_TOK  = 0;
constexpr size_t OFF_DEC  = OFF_TOK  + (size_t)TTOK*96;
constexpr size_t OFF_ENC  = OFF_DEC  + (size_t)TTOK*96;
constexpr size_t OFF_RAW  = OFF_ENC  + (size_t)TTOK*DM;
constexpr size_t OFF_XZB  = OFF_RAW  + (size_t)TTOK*DM;        // [T, 2048]
constexpr size_t OFF_XC0  = OFF_XZB  + (size_t)TTOK*4*DM;
constexpr size_t OFF_XC1  = OFF_XC0  + (size_t)TTOK*DM;
constexpr size_t OFF_DBL0 = OFF_XC1  + (size_t)TTOK*DM;        // [T,544]
constexpr size_t OFF_DBL1 = OFF_DBL0 + (size_t)TTOK*544;
constexpr size_t OFF_YP0  = OFF_DBL1 + (size_t)TTOK*544;
constexpr size_t OFF_YP1  = OFF_YP0  + (size_t)TTOK*DM;
constexpr size_t OFF_MO0  = OFF_YP1  + (size_t)TTOK*DM;
constexpr size_t OFF_MO1  = OFF_MO0  + (size_t)TTOK*DM;
constexpr size_t OFF_T1   = OFF_MO1  + (size_t)TTOK*DM;
constexpr size_t OFF_T2   = OFF_T1   + (size_t)TTOK*DM;
constexpr size_t OFF_T3   = OFF_T2   + (size_t)TTOK*DM;
constexpr size_t OFF_WCOMB= OFF_T3   + (size_t)TTOK*DM;        // [4,544,512]
constexpr size_t OFF_MEAN = OFF_WCOMB+ (size_t)4*544*512;
constexpr size_t OFF_STD  = OFF_MEAN + (size_t)BATCH*NVARS;
constexpr size_t SCRATCH_FLOATS = OFF_STD + (size_t)BATCH*NVARS;

__device__ float g_scratch[SCRATCH_FLOATS];

// ================= bf16-split tensor-core GEMM =============================
// C[M,N] = act(A[M,K(lda)] * W[N,K]^T + bias)
// 3-product bf16 split: hi*hi + lo*hi + hi*lo  (~1e-5 rel accuracy)
enum { ACT_NONE = 0, ACT_RELU = 1, ACT_DELTABC = 2, ACT_GATE = 3 };

#define BM 128
#define BN 128
#define BKF 32                      // fp32 k per chunk
#define LPITCH 36                   // u32 per smem row (72 bf16: hi[32] lo[32] pad[8])
#define ROWB 144                    // bytes per smem row
#define TILE_BYTES (128*ROWB)       // 18432
#define STAGE_BYTES (2*TILE_BYTES)  // A + B = 36864
#define SMEM_GEMM (2*STAGE_BYTES)   // 73728

__device__ __forceinline__ uint32_t smem_u32(const void* p) {
    uint32_t a;
    asm("{ .reg .u64 t; cvta.to.shared.u64 t, %1; cvt.u32.u64 %0, t; }"
        : "=r"(a) : "l"(p));
    return a;
}

__device__ __forceinline__ uint32_t pack_bf16(float a, float b) {
    __nv_bfloat162 t = __floats2bfloat162_rn(a, b);
    return *reinterpret_cast<uint32_t*>(&t);
}

#define LDSM_X4(r0,r1,r2,r3,addr) \
    asm volatile("ldmatrix.sync.aligned.m8n8.x4.shared.b16 {%0,%1,%2,%3}, [%4];" \
        : "=r"(r0),"=r"(r1),"=r"(r2),"=r"(r3) : "r"(addr))

#define MMA_BF16(d,a,b0,b1) \
    asm volatile("mma.sync.aligned.m16n8k16.row.col.f32.bf16.bf16.f32 " \
        "{%0,%1,%2,%3}, {%4,%5,%6,%7}, {%8,%9}, {%0,%1,%2,%3};" \
        : "+f"((d)[0]),"+f"((d)[1]),"+f"((d)[2]),"+f"((d)[3]) \
        : "r"((a)[0]),"r"((a)[1]),"r"((a)[2]),"r"((a)[3]), "r"(b0),"r"(b1))

template <int ACT>
__global__ void __launch_bounds__(256, 1)
mma_gemm(const float* __restrict__ A, int lda,
         const float* __restrict__ W,
         const float* __restrict__ bias,
         float* __restrict__ C, int ldc,
         int M, int N, int K,
         const float* __restrict__ e1, const float* __restrict__ e2)
{
    extern __shared__ char smem[];
    const uint32_t sbase = smem_u32(smem);
    const int tid  = threadIdx.x;
    const int lane = tid & 31;
    const int wid  = tid >> 5;
    const int warp_m = wid & 1;        // 2 x 64 rows
    const int warp_n = wid >> 1;       // 4 x 32 cols
    const int bm = blockIdx.y * BM, bn = blockIdx.x * BN;

    // global-load mapping: 8 float4 per 32-float row
    const int c4 = tid & 7;            // float4 index within row
    const int r0g = tid >> 3;          // base row (0..31), +32*i

    float4 aReg[4], bReg[4];

    auto load_global = [&](int kt) {
        const float* Ap = A + (size_t)kt * BKF + (size_t)c4 * 4;
        const float* Wp = W + (size_t)kt * BKF + (size_t)c4 * 4;
#pragma unroll
        for (int i = 0; i < 4; i++) {
            int row = r0g + i * 32;
            int gr = bm + row;
            aReg[i] = (gr < M) ? *reinterpret_cast<const float4*>(Ap + (size_t)gr * lda)
                               : make_float4(0.f, 0.f, 0.f, 0.f);
            int gn = bn + row;
            bReg[i] = (gn < N) ? *reinterpret_cast<const float4*>(Wp + (size_t)gn * K)
                               : make_float4(0.f, 0.f, 0.f, 0.f);
        }
    };

    auto store_stage = [&](int s) {
        uint32_t* sa = reinterpret_cast<uint32_t*>(smem + s * STAGE_BYTES);
        uint32_t* sb = reinterpret_cast<uint32_t*>(smem + s * STAGE_BYTES + TILE_BYTES);
#pragma unroll
        for (int i = 0; i < 4; i++) {
            int row = r0g + i * 32;
            {
                float4 v = aReg[i];
                float hx = __bfloat162float(__float2bfloat16_rn(v.x));
                float hy = __bfloat162float(__float2bfloat16_rn(v.y));
                float hz = __bfloat162float(__float2bfloat16_rn(v.z));
                float hw = __bfloat162float(__float2bfloat16_rn(v.w));
                uint32_t* p = sa + row * LPITCH + c4 * 2;
                p[0] = pack_bf16(hx, hy);
                p[1] = pack_bf16(hz, hw);
                p[16] = pack_bf16(v.x - hx, v.y - hy);
                p[17] = pack_bf16(v.z - hz, v.w - hw);
            }
            {
                float4 v = bReg[i];
                float hx = __bfloat162float(__float2bfloat16_rn(v.x));
                float hy = __bfloat162float(__float2bfloat16_rn(v.y));
                float hz = __bfloat162float(__float2bfloat16_rn(v.z));
                float hw = __bfloat162float(__float2bfloat16_rn(v.w));
                uint32_t* p = sb + row * LPITCH + c4 * 2;
                p[0] = pack_bf16(hx, hy);
                p[1] = pack_bf16(hz, hw);
                p[16] = pack_bf16(v.x - hx, v.y - hy);
                p[17] = pack_bf16(v.z - hz, v.w - hw);
            }
        }
    };

    // ldmatrix per-thread addressing
    const uint32_t a_off = (uint32_t)(warp_m * 64 + (lane & 15)) * ROWB + ((lane >> 4) * 16);
    const uint32_t b_off = (uint32_t)(warp_n * 32 + ((lane >> 4) & 1) * 8 + (lane & 7)) * ROWB
                         + (((lane >> 3) & 1) * 16);

    float acc[4][4][4];
#pragma unroll
    for (int i = 0; i < 4; i++)
#pragma unroll
        for (int j = 0; j < 4; j++)
#pragma unroll
            for (int e = 0; e < 4; e++) acc[i][j][e] = 0.f;

    const int KT = K / BKF;
    load_global(0);
    store_stage(0);
    __syncthreads();

    for (int kt = 0; kt < KT; kt++) {
        if (kt + 1 < KT) load_global(kt + 1);
        const uint32_t Ab = sbase + (kt & 1) * STAGE_BYTES;
        const uint32_t Bb = Ab + TILE_BYTES;
        // k-step -> (A segment, B segment): hi=0, lo=1 (segment stride 64B = 32 bf16)
        // products: hi*hi (ks 0,1) ; lo*hi (ks 2,3) ; hi*lo (ks 4,5)
#pragma unroll
        for (int ks = 0; ks < 6; ks++) {
            const int kk = ks & 1;
            const int segA = (ks == 2 || ks == 3) ? 1 : 0;
            const int segB = (ks >= 4) ? 1 : 0;
            const uint32_t ao = Ab + a_off + segA * 64 + kk * 32;
            const uint32_t bo = Bb + b_off + segB * 64 + kk * 32;
            uint32_t a[4][4];
#pragma unroll
            for (int mt = 0; mt < 4; mt++)
                LDSM_X4(a[mt][0], a[mt][1], a[mt][2], a[mt][3], ao + mt * 16 * ROWB);
            uint32_t b[2][4];
#pragma unroll
            for (int p = 0; p < 2; p++)
                LDSM_X4(b[p][0], b[p][1], b[p][2], b[p][3], bo + p * 16 * ROWB);
#pragma unroll
            for (int mt = 0; mt < 4; mt++) {
                MMA_BF16(acc[mt][0], a[mt], b[0][0], b[0][1]);
                MMA_BF16(acc[mt][1], a[mt], b[0][2], b[0][3]);
                MMA_BF16(acc[mt][2], a[mt], b[1][0], b[1][1]);
                MMA_BF16(acc[mt][3], a[mt], b[1][2], b[1][3]);
            }
        }
        if (kt + 1 < KT) store_stage((kt + 1) & 1);
        __syncthreads();
    }

    // ---- epilogue ----
    const int er = bm + warp_m * 64 + (lane >> 2);
    const int ec = bn + warp_n * 32 + (lane & 3) * 2;
#pragma unroll
    for (int mt = 0; mt < 4; mt++) {
#pragma unroll
        for (int nt = 0; nt < 4; nt++) {
            int gc = ec + nt * 8;
            if (gc >= N) continue;
            float b0 = 0.f, b1 = 0.f;
            if (bias) {
                if (ACT == ACT_DELTABC) {
                    if (gc < 512)     b0 = bias[gc];
                    if (gc + 1 < 512) b1 = bias[gc + 1];
                } else {
                    b0 = bias[gc]; b1 = bias[gc + 1];
                }
            }
#pragma unroll
            for (int h = 0; h < 2; h++) {
                int gr = er + mt * 16 + h * 8;
                if (gr >= M) continue;
                float v0 = acc[mt][nt][h * 2 + 0];
                float v1 = acc[mt][nt][h * 2 + 1];
                if (ACT == ACT_NONE) {
                    v0 += b0; v1 += b1;
                } else if (ACT == ACT_RELU) {
                    v0 = fmaxf(v0 + b0, 0.f); v1 = fmaxf(v1 + b1, 0.f);
                } else if (ACT == ACT_DELTABC) {
                    if (gc < 512) {
                        v0 += b0;
                        v0 = fmaxf(v0, 0.f) + log1pf(__expf(-fabsf(v0)));
                    }
                    if (gc + 1 < 512) {
                        v1 += b1;
                        v1 = fmaxf(v1, 0.f) + log1pf(__expf(-fabsf(v1)));
                    }
                } else if (ACT == ACT_GATE) {
                    size_t ix = (size_t)gr * ldc + gc;
                    float s0 = 1.f / (1.f + __expf(-(v0 + b0)));
                    float s1 = 1.f / (1.f + __expf(-(v1 + b1)));
                    v0 = e1[ix] + s0 * e2[ix];
                    v1 = e1[ix + 1] + s1 * e2[ix + 1];
                }
                *reinterpret_cast<float2*>(&C[(size_t)gr * ldc + gc]) =
                    make_float2(v0, v1);
            }
        }
    }
}

// ================= small kernels ==========================================
__global__ void stats_kernel(const float* __restrict__ x_enc,
                             float* __restrict__ means, float* __restrict__ stds)
{
    int idx = blockIdx.x * blockDim.x + threadIdx.x;
    if (idx >= BATCH * NVARS) return;
    int b = idx / NVARS, n = idx - b * NVARS;
    float s = 0.f, sq = 0.f;
    for (int t = 0; t < SEQ; t++) {
        float v = x_enc[((size_t)b * SEQ + t) * NVARS + n];
        s += v; sq += v * v;
    }
    float m = s * (1.f / SEQ);
    float var = sq * (1.f / SEQ) - m * m;
    means[idx] = m;
    stds[idx] = sqrtf(var + 1e-5f);
}

__global__ void tok_kernel(const float* __restrict__ x_enc,
                           const float* __restrict__ x_mark,
                           const float* __restrict__ means,
                           const float* __restrict__ stds,
                           float* __restrict__ tok)
{
    int idx = blockIdx.x * blockDim.x + threadIdx.x;
    if (idx >= TTOK * SEQ) return;
    int sIdx = idx % SEQ;
    int t = idx / SEQ;
    int b = t / LTOK, v = t - b * LTOK;
    float val;
    if (v < NVARS) {
        val = (x_enc[((size_t)b * SEQ + sIdx) * NVARS + v] - means[b * NVARS + v])
              / stds[b * NVARS + v];
    } else {
        val = x_mark[((size_t)b * SEQ + sIdx) * NMARK + (v - NVARS)];
    }
    tok[idx] = val;
}

// W_comb[w][n][k]: n<512 -> sum_r dtw[w,n,r]*xpw[w,r,k];  n>=512 -> xpw[w,32+n-512,k]
__global__ void wcomb_kernel(const float* __restrict__ dtw,
                             const float* __restrict__ xpw,
                             float* __restrict__ wcomb)
{
    int idx = blockIdx.x * blockDim.x + threadIdx.x;
    if (idx >= 4 * 544 * 512) return;
    int w = idx / (544 * 512);
    int rem = idx - w * 544 * 512;
    int n = rem >> 9;
    int k = rem & 511;
    float v;
    if (n < 512) {
        const float* dr = dtw + ((size_t)w * 512 + n) * 32;
        const float* xr = xpw + (size_t)w * 64 * 512 + k;
        v = 0.f;
#pragma unroll
        for (int r = 0; r < 32; r++) v = fmaf(dr[r], xr[(size_t)r * 512], v);
    } else {
        v = xpw[(size_t)w * 64 * 512 + (size_t)(32 + n - 512) * 512 + k];
    }
    wcomb[idx] = v;
}

// depthwise conv(2) + SiLU, both dirs. xzB: [T, 2048] = [xi0|z0|xi1|z1]
__global__ void conv_silu_kernel(const float* __restrict__ xzB,
                                 const float* __restrict__ cw,   // [2,DM,2]
                                 const float* __restrict__ cb,   // [2,DM]
                                 float* __restrict__ xc0, float* __restrict__ xc1)
{
    int idx = blockIdx.x * blockDim.x + threadIdx.x;
    const int n = TTOK * DM;
    if (idx >= 2 * n) return;
    int dir = idx >= n;
    int r = idx - dir * n;
    int d = r & (DM - 1);
    int t = r >> 9;
    int b = t / LTOK, l = t - b * LTOK;
    const float* base = xzB + (size_t)dir * 2 * DM;   // xi block for this dir
    float cur = base[(size_t)t * (4 * DM) + d];
    int ln = dir ? (l + 1) : (l - 1);
    float nb = 0.f;
    if (ln >= 0 && ln < LTOK)
        nb = base[(size_t)(t + (dir ? 1 : -1)) * (4 * DM) + d];
    float w0 = cw[(size_t)dir * DM * 2 + d * 2 + 0];
    float w1 = cw[(size_t)dir * DM * 2 + d * 2 + 1];
    float v = w0 * nb + w1 * cur + cb[dir * DM + d];
    float out = v / (1.f + __expf(-v));
    (dir ? xc1 : xc0)[r] = out;
}

// selective scan: 16-lane group per (b,d). dblD: [T,544] (delta 512 | B 16 | C 16)
__global__ void __launch_bounds__(256)
scan_kernel(const float* __restrict__ dblD,
            const float* __restrict__ xc,
            const float* __restrict__ xzB,   // z at col dir*1024 + 512 + d
            const float* __restrict__ A_log,
            const float* __restrict__ Dp,
            float* __restrict__ ypre, int dir)
{
    int gid = blockIdx.x * (blockDim.x >> 4) + (threadIdx.x >> 4);
    int s = threadIdx.x & 15;
    int b = gid >> 9;
    int d = gid & (DM - 1);
    float a = -__expf(A_log[d * DS + s]);
    float Dv = Dp[d];
    float h = 0.f;
    size_t base = (size_t)b * LTOK;
    const size_t zoff = (size_t)dir * 2 * DM + DM;
    for (int i = 0; i < LTOK; i++) {
        int l = dir ? (LTOK - 1 - i) : i;
        size_t t = base + l;
        float dlt = dblD[t * 544 + d];
        float x   = xc[t * DM + d];
        float bm  = dblD[t * 544 + 512 + s];
        float cm  = dblD[t * 544 + 528 + s];
        float dA = __expf(dlt * a);
        h = dA * h + (dlt * bm) * x;
        float p = h * cm;
        p += __shfl_xor_sync(0xffffffffu, p, 1);
        p += __shfl_xor_sync(0xffffffffu, p, 2);
        p += __shfl_xor_sync(0xffffffffu, p, 4);
        p += __shfl_xor_sync(0xffffffffu, p, 8);
        if (s == 0) {
            float z = xzB[t * (4 * DM) + zoff + d];
            float sz = z / (1.f + __expf(-z));
            ypre[t * DM + d] = (p + Dv * x) * sz;
        }
    }
}

__global__ void ln_kernel(const float* __restrict__ i1,
                          const float* __restrict__ i2,
                          const float* __restrict__ i3,
                          const float* __restrict__ g,
                          const float* __restrict__ bta,
                          float* __restrict__ out)
{
    int row = blockIdx.x * (blockDim.x >> 5) + (threadIdx.x >> 5);
    int lane = threadIdx.x & 31;
    if (row >= TTOK) return;
    size_t rb = (size_t)row * DM;
    float vals[16];
    float s = 0.f, sq = 0.f;
#pragma unroll
    for (int i = 0; i < 16; i++) {
        int c = lane + i * 32;
        float v = i1[rb + c];
        if (i2) v += i2[rb + c];
        if (i3) v += i3[rb + c];
        vals[i] = v; s += v; sq += v * v;
    }
#pragma unroll
    for (int o = 16; o; o >>= 1) {
        s  += __shfl_xor_sync(0xffffffffu, s, o);
        sq += __shfl_xor_sync(0xffffffffu, sq, o);
    }
    float m = s * (1.f / DM);
    float var = sq * (1.f / DM) - m * m;
    float r = rsqrtf(var + 1e-5f);
#pragma unroll
    for (int i = 0; i < 16; i++) {
        int c = lane + i * 32;
        out[rb + c] = (vals[i] - m) * r * g[c] + bta[c];
    }
}

__global__ void out_kernel(const float* __restrict__ dec,
                           const float* __restrict__ means,
                           const float* __restrict__ stds,
                           float* __restrict__ out)
{
    int idx = blockIdx.x * blockDim.x + threadIdx.x;
    if (idx >= BATCH * PRED * NVARS) return;
    int b = idx / (PRED * NVARS);
    int rem = idx - b * (PRED * NVARS);
    int p = rem / NVARS;
    int n = rem - p * NVARS;
    float v = dec[((size_t)b * LTOK + n) * PRED + p];
    out[idx] = v * stds[b * NVARS + n] + means[b * NVARS + n];
}

// ================= host orchestration ======================================
template <int ACT>
static void launch_mma(const float* A, int lda, const float* W, const float* bias,
                       float* C, int ldc, int M, int N, int K,
                       const float* e1 = nullptr, const float* e2 = nullptr)
{
    dim3 grid(CDIV(N, BN), CDIV(M, BM));
    mma_gemm<ACT><<<grid, 256, SMEM_GEMM>>>(A, lda, W, bias, C, ldc, M, N, K, e1, e2);
}

extern "C" void kernel_launch(void* const* d_in, const int* in_sizes, int n_in,
                              void* d_out, int out_size)
{
    const float* x_enc    = (const float*)d_in[0];
    const float* x_mark   = (const float*)d_in[1];
    const float* emb_w    = (const float*)d_in[4];
    const float* emb_b    = (const float*)d_in[5];
    const float* in_proj  = (const float*)d_in[6];
    const float* conv_w   = (const float*)d_in[7];
    const float* conv_b   = (const float*)d_in[8];
    const float* x_proj   = (const float*)d_in[9];
    const float* dt_w     = (const float*)d_in[10];
    const float* dt_b     = (const float*)d_in[11];
    const float* A_log    = (const float*)d_in[12];
    const float* D_param  = (const float*)d_in[13];
    const float* out_w    = (const float*)d_in[14];
    const float* ffn_w1   = (const float*)d_in[15];
    const float* ffn_b1   = (const float*)d_in[16];
    const float* ffn_w2   = (const float*)d_in[17];
    const float* ffn_b2   = (const float*)d_in[18];
    const float* ln1_g    = (const float*)d_in[19];
    const float* ln1_b    = (const float*)d_in[20];
    const float* ln2_g    = (const float*)d_in[21];
    const float* ln2_b    = (const float*)d_in[22];
    const float* fin_g    = (const float*)d_in[23];
    const float* fin_b    = (const float*)d_in[24];
    const float* gate_w   = (const float*)d_in[25];
    const float* gate_b   = (const float*)d_in[26];
    const float* proj_w   = (const float*)d_in[27];
    const float* proj_b   = (const float*)d_in[28];

    cudaFuncSetAttribute(mma_gemm<ACT_NONE>,    cudaFuncAttributeMaxDynamicSharedMemorySize, SMEM_GEMM);
    cudaFuncSetAttribute(mma_gemm<ACT_RELU>,    cudaFuncAttributeMaxDynamicSharedMemorySize, SMEM_GEMM);
    cudaFuncSetAttribute(mma_gemm<ACT_DELTABC>, cudaFuncAttributeMaxDynamicSharedMemorySize, SMEM_GEMM);
    cudaFuncSetAttribute(mma_gemm<ACT_GATE>,    cudaFuncAttributeMaxDynamicSharedMemorySize, SMEM_GEMM);

    float* S = nullptr;
    cudaGetSymbolAddress((void**)&S, g_scratch);

    float* tok   = S + OFF_TOK;
    float* dec   = S + OFF_DEC;
    float* enc   = S + OFF_ENC;
    float* raw   = S + OFF_RAW;
    float* xzB   = S + OFF_XZB;
    float* xcb[2] = { S + OFF_XC0,  S + OFF_XC1 };
    float* dbl[2] = { S + OFF_DBL0, S + OFF_DBL1 };
    float* yp[2]  = { S + OFF_YP0,  S + OFF_YP1 };
    float* mo[2]  = { S + OFF_MO0,  S + OFF_MO1 };
    float* t1    = S + OFF_T1;
    float* t2    = S + OFF_T2;
    float* t3    = S + OFF_T3;
    float* wcomb = S + OFF_WCOMB;
    float* means = S + OFF_MEAN;
    float* stds  = S + OFF_STD;

    stats_kernel<<<CDIV(BATCH * NVARS, 256), 256>>>(x_enc, means, stds);
    tok_kernel<<<CDIV(TTOK * SEQ, 256), 256>>>(x_enc, x_mark, means, stds, tok);
    wcomb_kernel<<<CDIV(4 * 544 * 512, 256), 256>>>(dt_w, x_proj, wcomb);

    // embedding GEMM -> enc
    launch_mma<ACT_NONE>(tok, SEQ, emb_w, emb_b, enc, DM, TTOK, DM, SEQ);
    cudaMemcpyAsync(raw, enc, (size_t)TTOK * DM * sizeof(float),
                    cudaMemcpyDeviceToDevice);

    for (int l = 0; l < NL; l++) {
        // merged fwd+rev in_proj: N=2048
        launch_mma<ACT_NONE>(enc, DM, in_proj + (size_t)l * 2 * 2 * DM * DM,
                             nullptr, xzB, 4 * DM, TTOK, 4 * DM, DM);
        conv_silu_kernel<<<CDIV(2 * TTOK * DM, 256), 256>>>(
            xzB, conv_w + (size_t)l * 2 * DM * 2, conv_b + (size_t)l * 2 * DM,
            xcb[0], xcb[1]);
        for (int dir = 0; dir < 2; dir++) {
            int w = l * 2 + dir;
            // fused delta(softplus)+B+C GEMM: N=544
            launch_mma<ACT_DELTABC>(xcb[dir], DM, wcomb + (size_t)w * 544 * 512,
                                    dt_b + (size_t)w * DM, dbl[dir], 544,
                                    TTOK, 544, DM);
            scan_kernel<<<(BATCH * DM * 16) / 256, 256>>>(
                dbl[dir], xcb[dir], xzB,
                A_log + (size_t)w * DM * DS, D_param + (size_t)w * DM,
                yp[dir], dir);
            launch_mma<ACT_NONE>(yp[dir], DM, out_w + (size_t)w * DM * DM,
                                 nullptr, mo[dir], DM, TTOK, DM, DM);
        }
        ln_kernel<<<CDIV(TTOK, 8), 256>>>(enc, mo[0], mo[1],
                                          ln1_g + l * DM, ln1_b + l * DM, t1);
        launch_mma<ACT_RELU>(t1, DM, ffn_w1 + (size_t)l * DFF * DM,
                             ffn_b1 + l * DFF, t2, DFF, TTOK, DFF, DM);
        launch_mma<ACT_NONE>(t2, DFF, ffn_w2 + (size_t)l * DM * DFF,
                             ffn_b2 + l * DM, t3, DM, TTOK, DM, DFF);
        ln_kernel<<<CDIV(TTOK, 8), 256>>>(t1, t3, nullptr,
                                          ln2_g + l * DM, ln2_b + l * DM, enc);
    }

    ln_kernel<<<CDIV(TTOK, 8), 256>>>(enc, nullptr, nullptr, fin_g, fin_b, t2);
    launch_mma<ACT_GATE>(raw, DM, gate_w, gate_b, t1, DM, TTOK, DM, DM, t2, raw);
    launch_mma<ACT_NONE>(t1, DM, proj_w, proj_b, dec, PRED, TTOK, PRED, DM);
    out_kernel<<<CDIV(BATCH * PRED * NVARS, 256), 256>>>(dec, means, stds,
                                                         (float*)d_out);
}

// round 4
// speedup vs baseline: 2.0214x; 1.6443x over previous
#include <cuda_runtime.h>
#include <cuda_bf16.h>
#include <math.h>
#include <stdint.h>

// ---------------- problem constants ----------------
#define BATCH 8
#define SEQ   96
#define PRED  96
#define NVARS 862
#define NMARK 4
#define LTOK  866
#define TTOK  (BATCH*LTOK)   // 6928
#define DM    512
#define DS    16
#define DFF   512
#define RK    32
#define NL    2

// chunked scan
#define NCH   16
#define CHL   55             // 16*55 = 880 >= 866
#define NGRP  (2*BATCH*DM*NCH)      // 131072 groups (dir,b,d,ch)
#define NSTATE ((size_t)NGRP*16)    // per-(group,s) states

#define CDIV(a,b) (((a)+(b)-1)/(b))

// ================= scratch (static; no allocs) =============================
constexpr size_t OFF_TOK  = 0;
constexpr size_t OFF_DEC  = OFF_TOK  + (size_t)TTOK*96;
constexpr size_t OFF_ENC  = OFF_DEC  + (size_t)TTOK*96;
constexpr size_t OFF_RAW  = OFF_ENC  + (size_t)TTOK*DM;
constexpr size_t OFF_XZB  = OFF_RAW  + (size_t)TTOK*DM;        // [T, 2048]
constexpr size_t OFF_XC0  = OFF_XZB  + (size_t)TTOK*4*DM;
constexpr size_t OFF_XC1  = OFF_XC0  + (size_t)TTOK*DM;
constexpr size_t OFF_DBL0 = OFF_XC1  + (size_t)TTOK*DM;        // [T,544]
constexpr size_t OFF_DBL1 = OFF_DBL0 + (size_t)TTOK*544;
constexpr size_t OFF_YP0  = OFF_DBL1 + (size_t)TTOK*544;
constexpr size_t OFF_YP1  = OFF_YP0  + (size_t)TTOK*DM;
constexpr size_t OFF_MO0  = OFF_YP1  + (size_t)TTOK*DM;
constexpr size_t OFF_MO1  = OFF_MO0  + (size_t)TTOK*DM;
constexpr size_t OFF_T1   = OFF_MO1  + (size_t)TTOK*DM;
constexpr size_t OFF_T2   = OFF_T1   + (size_t)TTOK*DM;
constexpr size_t OFF_T3   = OFF_T2   + (size_t)TTOK*DM;
constexpr size_t OFF_WCOMB= OFF_T3   + (size_t)TTOK*DM;        // [4,544,512]
constexpr size_t OFF_MEAN = OFF_WCOMB+ (size_t)4*544*512;
constexpr size_t OFF_STD  = OFF_MEAN + (size_t)BATCH*NVARS;
constexpr size_t OFF_P    = OFF_STD  + (size_t)BATCH*NVARS;
constexpr size_t OFF_HL   = OFF_P    + NSTATE;
constexpr size_t OFF_HI   = OFF_HL   + NSTATE;
constexpr size_t SCRATCH_FLOATS = OFF_HI + NSTATE;

__device__ float g_scratch[SCRATCH_FLOATS];

// ================= bf16-split tensor-core GEMM =============================
// C[M,N] = act(A[M,K(lda)] * W[N,K]^T + bias)
// 3-product bf16 split: hi*hi + lo*hi + hi*lo  (~1e-5 rel accuracy)
// Optional z-batching: pointers advance by per-z element strides.
enum { ACT_NONE = 0, ACT_RELU = 1, ACT_DELTABC = 2, ACT_GATE = 3 };

#define BM 128
#define BN 128
#define BKF 32                      // fp32 k per chunk
#define LPITCH 36                   // u32 per smem row (72 bf16: hi[32] lo[32] pad[8])
#define ROWB 144                    // bytes per smem row
#define TILE_BYTES (128*ROWB)       // 18432
#define STAGE_BYTES (2*TILE_BYTES)  // A + B = 36864
#define SMEM_GEMM (2*STAGE_BYTES)   // 73728

__device__ __forceinline__ uint32_t smem_u32(const void* p) {
    uint32_t a;
    asm("{ .reg .u64 t; cvta.to.shared.u64 t, %1; cvt.u32.u64 %0, t; }"
        : "=r"(a) : "l"(p));
    return a;
}

__device__ __forceinline__ uint32_t pack_bf16(float a, float b) {
    __nv_bfloat162 t = __floats2bfloat162_rn(a, b);
    return *reinterpret_cast<uint32_t*>(&t);
}

#define LDSM_X4(r0,r1,r2,r3,addr) \
    asm volatile("ldmatrix.sync.aligned.m8n8.x4.shared.b16 {%0,%1,%2,%3}, [%4];" \
        : "=r"(r0),"=r"(r1),"=r"(r2),"=r"(r3) : "r"(addr))

#define MMA_BF16(d,a,b0,b1) \
    asm volatile("mma.sync.aligned.m16n8k16.row.col.f32.bf16.bf16.f32 " \
        "{%0,%1,%2,%3}, {%4,%5,%6,%7}, {%8,%9}, {%0,%1,%2,%3};" \
        : "+f"((d)[0]),"+f"((d)[1]),"+f"((d)[2]),"+f"((d)[3]) \
        : "r"((a)[0]),"r"((a)[1]),"r"((a)[2]),"r"((a)[3]), "r"(b0),"r"(b1))

template <int ACT>
__global__ void __launch_bounds__(256, 1)
mma_gemm(const float* __restrict__ A, int lda,
         const float* __restrict__ W,
         const float* __restrict__ bias,
         float* __restrict__ C, int ldc,
         int M, int N, int K,
         const float* __restrict__ e1, const float* __restrict__ e2,
         size_t zsA, size_t zsW, size_t zsC, size_t zsBias)
{
    extern __shared__ char smem[];
    const uint32_t sbase = smem_u32(smem);
    const int tid  = threadIdx.x;
    const int lane = tid & 31;
    const int wid  = tid >> 5;
    const int warp_m = wid & 1;        // 2 x 64 rows
    const int warp_n = wid >> 1;       // 4 x 32 cols
    const int bm = blockIdx.y * BM, bn = blockIdx.x * BN;

    A += blockIdx.z * zsA;
    W += blockIdx.z * zsW;
    C += blockIdx.z * zsC;
    if (bias) bias += blockIdx.z * zsBias;

    // global-load mapping: 8 float4 per 32-float row
    const int c4 = tid & 7;            // float4 index within row
    const int r0g = tid >> 3;          // base row (0..31), +32*i

    float4 aReg[4], bReg[4];

    auto load_global = [&](int kt) {
        const float* Ap = A + (size_t)kt * BKF + (size_t)c4 * 4;
        const float* Wp = W + (size_t)kt * BKF + (size_t)c4 * 4;
#pragma unroll
        for (int i = 0; i < 4; i++) {
            int row = r0g + i * 32;
            int gr = bm + row;
            aReg[i] = (gr < M) ? *reinterpret_cast<const float4*>(Ap + (size_t)gr * lda)
                               : make_float4(0.f, 0.f, 0.f, 0.f);
            int gn = bn + row;
            bReg[i] = (gn < N) ? *reinterpret_cast<const float4*>(Wp + (size_t)gn * K)
                               : make_float4(0.f, 0.f, 0.f, 0.f);
        }
    };

    auto store_stage = [&](int s) {
        uint32_t* sa = reinterpret_cast<uint32_t*>(smem + s * STAGE_BYTES);
        uint32_t* sb = reinterpret_cast<uint32_t*>(smem + s * STAGE_BYTES + TILE_BYTES);
#pragma unroll
        for (int i = 0; i < 4; i++) {
            int row = r0g + i * 32;
            {
                float4 v = aReg[i];
                float hx = __bfloat162float(__float2bfloat16_rn(v.x));
                float hy = __bfloat162float(__float2bfloat16_rn(v.y));
                float hz = __bfloat162float(__float2bfloat16_rn(v.z));
                float hw = __bfloat162float(__float2bfloat16_rn(v.w));
                uint32_t* p = sa + row * LPITCH + c4 * 2;
                p[0] = pack_bf16(hx, hy);
                p[1] = pack_bf16(hz, hw);
                p[16] = pack_bf16(v.x - hx, v.y - hy);
                p[17] = pack_bf16(v.z - hz, v.w - hw);
            }
            {
                float4 v = bReg[i];
                float hx = __bfloat162float(__float2bfloat16_rn(v.x));
                float hy = __bfloat162float(__float2bfloat16_rn(v.y));
                float hz = __bfloat162float(__float2bfloat16_rn(v.z));
                float hw = __bfloat162float(__float2bfloat16_rn(v.w));
                uint32_t* p = sb + row * LPITCH + c4 * 2;
                p[0] = pack_bf16(hx, hy);
                p[1] = pack_bf16(hz, hw);
                p[16] = pack_bf16(v.x - hx, v.y - hy);
                p[17] = pack_bf16(v.z - hz, v.w - hw);
            }
        }
    };

    // ldmatrix per-thread addressing
    const uint32_t a_off = (uint32_t)(warp_m * 64 + (lane & 15)) * ROWB + ((lane >> 4) * 16);
    const uint32_t b_off = (uint32_t)(warp_n * 32 + ((lane >> 4) & 1) * 8 + (lane & 7)) * ROWB
                         + (((lane >> 3) & 1) * 16);

    float acc[4][4][4];
#pragma unroll
    for (int i = 0; i < 4; i++)
#pragma unroll
        for (int j = 0; j < 4; j++)
#pragma unroll
            for (int e = 0; e < 4; e++) acc[i][j][e] = 0.f;

    const int KT = K / BKF;
    load_global(0);
    store_stage(0);
    __syncthreads();

    for (int kt = 0; kt < KT; kt++) {
        if (kt + 1 < KT) load_global(kt + 1);
        const uint32_t Ab = sbase + (kt & 1) * STAGE_BYTES;
        const uint32_t Bb = Ab + TILE_BYTES;
        // products: hi*hi (ks 0,1) ; lo*hi (ks 2,3) ; hi*lo (ks 4,5)
#pragma unroll
        for (int ks = 0; ks < 6; ks++) {
            const int kk = ks & 1;
            const int segA = (ks == 2 || ks == 3) ? 1 : 0;
            const int segB = (ks >= 4) ? 1 : 0;
            const uint32_t ao = Ab + a_off + segA * 64 + kk * 32;
            const uint32_t bo = Bb + b_off + segB * 64 + kk * 32;
            uint32_t a[4][4];
#pragma unroll
            for (int mt = 0; mt < 4; mt++)
                LDSM_X4(a[mt][0], a[mt][1], a[mt][2], a[mt][3], ao + mt * 16 * ROWB);
            uint32_t b[2][4];
#pragma unroll
            for (int p = 0; p < 2; p++)
                LDSM_X4(b[p][0], b[p][1], b[p][2], b[p][3], bo + p * 16 * ROWB);
#pragma unroll
            for (int mt = 0; mt < 4; mt++) {
                MMA_BF16(acc[mt][0], a[mt], b[0][0], b[0][1]);
                MMA_BF16(acc[mt][1], a[mt], b[0][2], b[0][3]);
                MMA_BF16(acc[mt][2], a[mt], b[1][0], b[1][1]);
                MMA_BF16(acc[mt][3], a[mt], b[1][2], b[1][3]);
            }
        }
        if (kt + 1 < KT) store_stage((kt + 1) & 1);
        __syncthreads();
    }

    // ---- epilogue ----
    const int er = bm + warp_m * 64 + (lane >> 2);
    const int ec = bn + warp_n * 32 + (lane & 3) * 2;
#pragma unroll
    for (int mt = 0; mt < 4; mt++) {
#pragma unroll
        for (int nt = 0; nt < 4; nt++) {
            int gc = ec + nt * 8;
            if (gc >= N) continue;
            float b0 = 0.f, b1 = 0.f;
            if (bias) {
                if (ACT == ACT_DELTABC) {
                    if (gc < 512)     b0 = bias[gc];
                    if (gc + 1 < 512) b1 = bias[gc + 1];
                } else {
                    b0 = bias[gc]; b1 = bias[gc + 1];
                }
            }
#pragma unroll
            for (int h = 0; h < 2; h++) {
                int gr = er + mt * 16 + h * 8;
                if (gr >= M) continue;
                float v0 = acc[mt][nt][h * 2 + 0];
                float v1 = acc[mt][nt][h * 2 + 1];
                if (ACT == ACT_NONE) {
                    v0 += b0; v1 += b1;
                } else if (ACT == ACT_RELU) {
                    v0 = fmaxf(v0 + b0, 0.f); v1 = fmaxf(v1 + b1, 0.f);
                } else if (ACT == ACT_DELTABC) {
                    if (gc < 512) {
                        v0 += b0;
                        v0 = fmaxf(v0, 0.f) + log1pf(__expf(-fabsf(v0)));
                    }
                    if (gc + 1 < 512) {
                        v1 += b1;
                        v1 = fmaxf(v1, 0.f) + log1pf(__expf(-fabsf(v1)));
                    }
                } else if (ACT == ACT_GATE) {
                    size_t ix = (size_t)gr * ldc + gc;
                    float s0 = 1.f / (1.f + __expf(-(v0 + b0)));
                    float s1 = 1.f / (1.f + __expf(-(v1 + b1)));
                    v0 = e1[ix] + s0 * e2[ix];
                    v1 = e1[ix + 1] + s1 * e2[ix + 1];
                }
                *reinterpret_cast<float2*>(&C[(size_t)gr * ldc + gc]) =
                    make_float2(v0, v1);
            }
        }
    }
}

// ================= small kernels ==========================================
__global__ void stats_kernel(const float* __restrict__ x_enc,
                             float* __restrict__ means, float* __restrict__ stds)
{
    int idx = blockIdx.x * blockDim.x + threadIdx.x;
    if (idx >= BATCH * NVARS) return;
    int b = idx / NVARS, n = idx - b * NVARS;
    float s = 0.f, sq = 0.f;
    for (int t = 0; t < SEQ; t++) {
        float v = x_enc[((size_t)b * SEQ + t) * NVARS + n];
        s += v; sq += v * v;
    }
    float m = s * (1.f / SEQ);
    float var = sq * (1.f / SEQ) - m * m;
    means[idx] = m;
    stds[idx] = sqrtf(var + 1e-5f);
}

__global__ void tok_kernel(const float* __restrict__ x_enc,
                           const float* __restrict__ x_mark,
                           const float* __restrict__ means,
                           const float* __restrict__ stds,
                           float* __restrict__ tok)
{
    int idx = blockIdx.x * blockDim.x + threadIdx.x;
    if (idx >= TTOK * SEQ) return;
    int sIdx = idx % SEQ;
    int t = idx / SEQ;
    int b = t / LTOK, v = t - b * LTOK;
    float val;
    if (v < NVARS) {
        val = (x_enc[((size_t)b * SEQ + sIdx) * NVARS + v] - means[b * NVARS + v])
              / stds[b * NVARS + v];
    } else {
        val = x_mark[((size_t)b * SEQ + sIdx) * NMARK + (v - NVARS)];
    }
    tok[idx] = val;
}

// W_comb[w][n][k]: n<512 -> sum_r dtw[w,n,r]*xpw[w,r,k];  n>=512 -> xpw[w,32+n-512,k]
__global__ void wcomb_kernel(const float* __restrict__ dtw,
                             const float* __restrict__ xpw,
                             float* __restrict__ wcomb)
{
    int idx = blockIdx.x * blockDim.x + threadIdx.x;
    if (idx >= 4 * 544 * 512) return;
    int w = idx / (544 * 512);
    int rem = idx - w * 544 * 512;
    int n = rem >> 9;
    int k = rem & 511;
    float v;
    if (n < 512) {
        const float* dr = dtw + ((size_t)w * 512 + n) * 32;
        const float* xr = xpw + (size_t)w * 64 * 512 + k;
        v = 0.f;
#pragma unroll
        for (int r = 0; r < 32; r++) v = fmaf(dr[r], xr[(size_t)r * 512], v);
    } else {
        v = xpw[(size_t)w * 64 * 512 + (size_t)(32 + n - 512) * 512 + k];
    }
    wcomb[idx] = v;
}

// depthwise conv(2) + SiLU, both dirs. xzB: [T, 2048] = [xi0|z0|xi1|z1]
__global__ void conv_silu_kernel(const float* __restrict__ xzB,
                                 const float* __restrict__ cw,   // [2,DM,2]
                                 const float* __restrict__ cb,   // [2,DM]
                                 float* __restrict__ xc0, float* __restrict__ xc1)
{
    int idx = blockIdx.x * blockDim.x + threadIdx.x;
    const int n = TTOK * DM;
    if (idx >= 2 * n) return;
    int dir = idx >= n;
    int r = idx - dir * n;
    int d = r & (DM - 1);
    int t = r >> 9;
    int b = t / LTOK, l = t - b * LTOK;
    const float* base = xzB + (size_t)dir * 2 * DM;   // xi block for this dir
    float cur = base[(size_t)t * (4 * DM) + d];
    int ln = dir ? (l + 1) : (l - 1);
    float nb = 0.f;
    if (ln >= 0 && ln < LTOK)
        nb = base[(size_t)(t + (dir ? 1 : -1)) * (4 * DM) + d];
    float w0 = cw[(size_t)dir * DM * 2 + d * 2 + 0];
    float w1 = cw[(size_t)dir * DM * 2 + d * 2 + 1];
    float v = w0 * nb + w1 * cur + cb[dir * DM + d];
    float out = v / (1.f + __expf(-v));
    (dir ? xc1 : xc0)[r] = out;
}

// ---------------- chunked selective scan ----------------------------------
// group gid = dir*65536 + b*8192 + d*16 + ch ; lane s = state index.
// Pass 1: per-chunk local scan -> P = prod(dA), Hl = local end state.
__global__ void __launch_bounds__(256)
scan_p1(const float* __restrict__ dbl0, const float* __restrict__ dbl1,
        const float* __restrict__ xc0,  const float* __restrict__ xc1,
        const float* __restrict__ A_log_l,   // [2,DM,DS]
        float* __restrict__ Pout, float* __restrict__ Hout)
{
    int gid = blockIdx.x * 16 + (threadIdx.x >> 4);
    int s = threadIdx.x & 15;
    int ch = gid & 15;
    int d = (gid >> 4) & (DM - 1);
    int b = (gid >> 13) & 7;
    int dir = gid >> 16;
    const float* dbl = dir ? dbl1 : dbl0;
    const float* xc  = dir ? xc1  : xc0;
    float a = -__expf(A_log_l[(size_t)dir * DM * DS + d * DS + s]);
    float h = 0.f, P = 1.f;
    size_t base = (size_t)b * LTOK;
    int i0 = ch * CHL;
    int i1 = i0 + CHL; if (i1 > LTOK) i1 = LTOK;
    for (int i = i0; i < i1; i++) {
        int l = dir ? (LTOK - 1 - i) : i;
        size_t t = base + l;
        float dlt = dbl[t * 544 + d];
        float x   = xc[t * DM + d];
        float bm  = dbl[t * 544 + 512 + s];
        float dA = __expf(dlt * a);
        P *= dA;
        h = dA * h + (dlt * bm) * x;
    }
    size_t o = (size_t)gid * 16 + s;
    Pout[o] = P;
    Hout[o] = h;
}

// Combine: serial over 16 chunks per (dir,b,d,s) -> per-chunk initial states.
__global__ void scan_comb(const float* __restrict__ P,
                          const float* __restrict__ Hl,
                          float* __restrict__ Hin)
{
    int idx = blockIdx.x * blockDim.x + threadIdx.x;   // (dir,b,d,s)
    if (idx >= 2 * BATCH * DM * 16) return;
    int s = idx & 15;
    int d = (idx >> 4) & (DM - 1);
    int b = (idx >> 13) & 7;
    int dir = idx >> 16;
    size_t gbase = (size_t)dir * 65536 + (size_t)b * 8192 + (size_t)d * 16;
    float h = 0.f;
#pragma unroll
    for (int ch = 0; ch < NCH; ch++) {
        size_t o = (gbase + ch) * 16 + s;
        Hin[o] = h;
        h = P[o] * h + Hl[o];
    }
}

// Pass 2: full per-chunk scan from Hin, producing gated outputs.
__global__ void __launch_bounds__(256)
scan_p2(const float* __restrict__ dbl0, const float* __restrict__ dbl1,
        const float* __restrict__ xc0,  const float* __restrict__ xc1,
        const float* __restrict__ xzB,
        const float* __restrict__ A_log_l,   // [2,DM,DS]
        const float* __restrict__ Dp_l,      // [2,DM]
        const float* __restrict__ Hin,
        float* __restrict__ yp0, float* __restrict__ yp1)
{
    int gid = blockIdx.x * 16 + (threadIdx.x >> 4);
    int s = threadIdx.x & 15;
    int ch = gid & 15;
    int d = (gid >> 4) & (DM - 1);
    int b = (gid >> 13) & 7;
    int dir = gid >> 16;
    const float* dbl = dir ? dbl1 : dbl0;
    const float* xc  = dir ? xc1  : xc0;
    float* yp        = dir ? yp1  : yp0;
    float a = -__expf(A_log_l[(size_t)dir * DM * DS + d * DS + s]);
    float Dv = Dp_l[dir * DM + d];
    float h = Hin[(size_t)gid * 16 + s];
    size_t base = (size_t)b * LTOK;
    const size_t zoff = (size_t)dir * 2 * DM + DM;
    int i0 = ch * CHL;
    int i1 = i0 + CHL; if (i1 > LTOK) i1 = LTOK;
    for (int i = i0; i < i1; i++) {
        int l = dir ? (LTOK - 1 - i) : i;
        size_t t = base + l;
        float dlt = dbl[t * 544 + d];
        float x   = xc[t * DM + d];
        float bm  = dbl[t * 544 + 512 + s];
        float cm  = dbl[t * 544 + 528 + s];
        float dA = __expf(dlt * a);
        h = dA * h + (dlt * bm) * x;
        float p = h * cm;
        p += __shfl_xor_sync(0xffffffffu, p, 1);
        p += __shfl_xor_sync(0xffffffffu, p, 2);
        p += __shfl_xor_sync(0xffffffffu, p, 4);
        p += __shfl_xor_sync(0xffffffffu, p, 8);
        if (s == 0) {
            float z = xzB[t * (4 * DM) + zoff + d];
            float sz = z / (1.f + __expf(-z));
            yp[t * DM + d] = (p + Dv * x) * sz;
        }
    }
}

__global__ void ln_kernel(const float* __restrict__ i1,
                          const float* __restrict__ i2,
                          const float* __restrict__ i3,
                          const float* __restrict__ g,
                          const float* __restrict__ bta,
                          float* __restrict__ out)
{
    int row = blockIdx.x * (blockDim.x >> 5) + (threadIdx.x >> 5);
    int lane = threadIdx.x & 31;
    if (row >= TTOK) return;
    size_t rb = (size_t)row * DM;
    float vals[16];
    float s = 0.f, sq = 0.f;
#pragma unroll
    for (int i = 0; i < 16; i++) {
        int c = lane + i * 32;
        float v = i1[rb + c];
        if (i2) v += i2[rb + c];
        if (i3) v += i3[rb + c];
        vals[i] = v; s += v; sq += v * v;
    }
#pragma unroll
    for (int o = 16; o; o >>= 1) {
        s  += __shfl_xor_sync(0xffffffffu, s, o);
        sq += __shfl_xor_sync(0xffffffffu, sq, o);
    }
    float m = s * (1.f / DM);
    float var = sq * (1.f / DM) - m * m;
    float r = rsqrtf(var + 1e-5f);
#pragma unroll
    for (int i = 0; i < 16; i++) {
        int c = lane + i * 32;
        out[rb + c] = (vals[i] - m) * r * g[c] + bta[c];
    }
}

__global__ void out_kernel(const float* __restrict__ dec,
                           const float* __restrict__ means,
                           const float* __restrict__ stds,
                           float* __restrict__ out)
{
    int idx = blockIdx.x * blockDim.x + threadIdx.x;
    if (idx >= BATCH * PRED * NVARS) return;
    int b = idx / (PRED * NVARS);
    int rem = idx - b * (PRED * NVARS);
    int p = rem / NVARS;
    int n = rem - p * NVARS;
    float v = dec[((size_t)b * LTOK + n) * PRED + p];
    out[idx] = v * stds[b * NVARS + n] + means[b * NVARS + n];
}

// ================= host orchestration ======================================
template <int ACT>
static void launch_mma(const float* A, int lda, const float* W, const float* bias,
                       float* C, int ldc, int M, int N, int K,
                       const float* e1 = nullptr, const float* e2 = nullptr,
                       int Z = 1, size_t zsA = 0, size_t zsW = 0,
                       size_t zsC = 0, size_t zsBias = 0)
{
    dim3 grid(CDIV(N, BN), CDIV(M, BM), Z);
    mma_gemm<ACT><<<grid, 256, SMEM_GEMM>>>(A, lda, W, bias, C, ldc, M, N, K,
                                            e1, e2, zsA, zsW, zsC, zsBias);
}

extern "C" void kernel_launch(void* const* d_in, const int* in_sizes, int n_in,
                              void* d_out, int out_size)
{
    const float* x_enc    = (const float*)d_in[0];
    const float* x_mark   = (const float*)d_in[1];
    const float* emb_w    = (const float*)d_in[4];
    const float* emb_b    = (const float*)d_in[5];
    const float* in_proj  = (const float*)d_in[6];
    const float* conv_w   = (const float*)d_in[7];
    const float* conv_b   = (const float*)d_in[8];
    const float* x_proj   = (const float*)d_in[9];
    const float* dt_w     = (const float*)d_in[10];
    const float* dt_b     = (const float*)d_in[11];
    const float* A_log    = (const float*)d_in[12];
    const float* D_param  = (const float*)d_in[13];
    const float* out_w    = (const float*)d_in[14];
    const float* ffn_w1   = (const float*)d_in[15];
    const float* ffn_b1   = (const float*)d_in[16];
    const float* ffn_w2   = (const float*)d_in[17];
    const float* ffn_b2   = (const float*)d_in[18];
    const float* ln1_g    = (const float*)d_in[19];
    const float* ln1_b    = (const float*)d_in[20];
    const float* ln2_g    = (const float*)d_in[21];
    const float* ln2_b    = (const float*)d_in[22];
    const float* fin_g    = (const float*)d_in[23];
    const float* fin_b    = (const float*)d_in[24];
    const float* gate_w   = (const float*)d_in[25];
    const float* gate_b   = (const float*)d_in[26];
    const float* proj_w   = (const float*)d_in[27];
    const float* proj_b   = (const float*)d_in[28];

    cudaFuncSetAttribute(mma_gemm<ACT_NONE>,    cudaFuncAttributeMaxDynamicSharedMemorySize, SMEM_GEMM);
    cudaFuncSetAttribute(mma_gemm<ACT_RELU>,    cudaFuncAttributeMaxDynamicSharedMemorySize, SMEM_GEMM);
    cudaFuncSetAttribute(mma_gemm<ACT_DELTABC>, cudaFuncAttributeMaxDynamicSharedMemorySize, SMEM_GEMM);
    cudaFuncSetAttribute(mma_gemm<ACT_GATE>,    cudaFuncAttributeMaxDynamicSharedMemorySize, SMEM_GEMM);

    float* S = nullptr;
    cudaGetSymbolAddress((void**)&S, g_scratch);

    float* tok   = S + OFF_TOK;
    float* dec   = S + OFF_DEC;
    float* enc   = S + OFF_ENC;
    float* raw   = S + OFF_RAW;
    float* xzB   = S + OFF_XZB;
    float* xcb[2] = { S + OFF_XC0,  S + OFF_XC1 };
    float* dbl[2] = { S + OFF_DBL0, S + OFF_DBL1 };
    float* yp[2]  = { S + OFF_YP0,  S + OFF_YP1 };
    float* mo[2]  = { S + OFF_MO0,  S + OFF_MO1 };
    float* t1    = S + OFF_T1;
    float* t2    = S + OFF_T2;
    float* t3    = S + OFF_T3;
    float* wcomb = S + OFF_WCOMB;
    float* means = S + OFF_MEAN;
    float* stds  = S + OFF_STD;
    float* Pbuf  = S + OFF_P;
    float* Hlbuf = S + OFF_HL;
    float* Hibuf = S + OFF_HI;

    stats_kernel<<<CDIV(BATCH * NVARS, 256), 256>>>(x_enc, means, stds);
    tok_kernel<<<CDIV(TTOK * SEQ, 256), 256>>>(x_enc, x_mark, means, stds, tok);
    wcomb_kernel<<<CDIV(4 * 544 * 512, 256), 256>>>(dt_w, x_proj, wcomb);

    // embedding GEMM -> enc
    launch_mma<ACT_NONE>(tok, SEQ, emb_w, emb_b, enc, DM, TTOK, DM, SEQ);
    cudaMemcpyAsync(raw, enc, (size_t)TTOK * DM * sizeof(float),
                    cudaMemcpyDeviceToDevice);

    for (int l = 0; l < NL; l++) {
        // merged fwd+rev in_proj: N=2048
        launch_mma<ACT_NONE>(enc, DM, in_proj + (size_t)l * 2 * 2 * DM * DM,
                             nullptr, xzB, 4 * DM, TTOK, 4 * DM, DM);
        conv_silu_kernel<<<CDIV(2 * TTOK * DM, 256), 256>>>(
            xzB, conv_w + (size_t)l * 2 * DM * 2, conv_b + (size_t)l * 2 * DM,
            xcb[0], xcb[1]);

        // fused delta(softplus)+B+C GEMM, both dirs batched (z=2)
        launch_mma<ACT_DELTABC>(xcb[0], DM, wcomb + (size_t)l * 2 * 544 * 512,
                                dt_b + (size_t)l * 2 * DM, dbl[0], 544,
                                TTOK, 544, DM, nullptr, nullptr,
                                2, (size_t)TTOK * DM, (size_t)544 * 512,
                                (size_t)TTOK * 544, DM);

        // chunked scan: pass1 -> combine -> pass2 (both dirs in each launch)
        scan_p1<<<NGRP / 16, 256>>>(dbl[0], dbl[1], xcb[0], xcb[1],
                                    A_log + (size_t)l * 2 * DM * DS,
                                    Pbuf, Hlbuf);
        scan_comb<<<CDIV(2 * BATCH * DM * 16, 256), 256>>>(Pbuf, Hlbuf, Hibuf);
        scan_p2<<<NGRP / 16, 256>>>(dbl[0], dbl[1], xcb[0], xcb[1], xzB,
                                    A_log + (size_t)l * 2 * DM * DS,
                                    D_param + (size_t)l * 2 * DM,
                                    Hibuf, yp[0], yp[1]);

        // out projection, both dirs batched (z=2)
        launch_mma<ACT_NONE>(yp[0], DM, out_w + (size_t)l * 2 * DM * DM,
                             nullptr, mo[0], DM, TTOK, DM, DM, nullptr, nullptr,
                             2, (size_t)TTOK * DM, (size_t)DM * DM,
                             (size_t)TTOK * DM, 0);

        ln_kernel<<<CDIV(TTOK, 8), 256>>>(enc, mo[0], mo[1],
                                          ln1_g + l * DM, ln1_b + l * DM, t1);
        launch_mma<ACT_RELU>(t1, DM, ffn_w1 + (size_t)l * DFF * DM,
                             ffn_b1 + l * DFF, t2, DFF, TTOK, DFF, DM);
        launch_mma<ACT_NONE>(t2, DFF, ffn_w2 + (size_t)l * DM * DFF,
                             ffn_b2 + l * DM, t3, DM, TTOK, DM, DFF);
        ln_kernel<<<CDIV(TTOK, 8), 256>>>(t1, t3, nullptr,
                                          ln2_g + l * DM, ln2_b + l * DM, enc);
    }

    ln_kernel<<<CDIV(TTOK, 8), 256>>>(enc, nullptr, nullptr, fin_g, fin_b, t2);
    launch_mma<ACT_GATE>(raw, DM, gate_w, gate_b, t1, DM, TTOK, DM, DM, t2, raw);
    launch_mma<ACT_NONE>(t1, DM, proj_w, proj_b, dec, PRED, TTOK, PRED, DM);
    out_kernel<<<CDIV(BATCH * PRED * NVARS, 256), 256>>>(dec, means, stds,
                                                         (float*)d_out);
}

// round 5
// speedup vs baseline: 3.1888x; 1.5775x over previous
#include <cuda_runtime.h>
#include <cuda_bf16.h>
#include <math.h>
#include <stdint.h>

// ---------------- problem constants ----------------
#define BATCH 8
#define SEQ   96
#define PRED  96
#define NVARS 862
#define NMARK 4
#define LTOK  866
#define TTOK  (BATCH*LTOK)   // 6928
#define DM    512
#define DS    16
#define DFF   512
#define RK    32
#define NL    2

// chunked scan: warp = 32 d-channels, 16 states/lane in registers
#define NCH   32
#define CHL   28             // 32*28 = 896 >= 866
#define NWARP (2*BATCH*16*NCH)          // 8192 warps (dir,b,dblk,ch)
#define NSTATE ((size_t)NWARP*32*16)    // 4.19M states

#define CDIV(a,b) (((a)+(b)-1)/(b))

// ================= scratch (static; no allocs) =============================
constexpr size_t OFF_TOK  = 0;
constexpr size_t OFF_DEC  = OFF_TOK  + (size_t)TTOK*96;
constexpr size_t OFF_ENC  = OFF_DEC  + (size_t)TTOK*96;
constexpr size_t OFF_RAW  = OFF_ENC  + (size_t)TTOK*DM;
constexpr size_t OFF_XZB  = OFF_RAW  + (size_t)TTOK*DM;        // [T, 2048]
constexpr size_t OFF_XC0  = OFF_XZB  + (size_t)TTOK*4*DM;
constexpr size_t OFF_XC1  = OFF_XC0  + (size_t)TTOK*DM;
constexpr size_t OFF_DX   = OFF_XC1  + (size_t)TTOK*DM;        // [T,2048] (dlt,x) pairs
constexpr size_t OFF_BC   = OFF_DX   + (size_t)TTOK*2048;      // [T,64] (B,C) pairs
constexpr size_t OFF_YP0  = OFF_BC   + (size_t)TTOK*64;
constexpr size_t OFF_YP1  = OFF_YP0  + (size_t)TTOK*DM;
constexpr size_t OFF_MO0  = OFF_YP1  + (size_t)TTOK*DM;
constexpr size_t OFF_MO1  = OFF_MO0  + (size_t)TTOK*DM;
constexpr size_t OFF_T1   = OFF_MO1  + (size_t)TTOK*DM;
constexpr size_t OFF_T2   = OFF_T1   + (size_t)TTOK*DM;
constexpr size_t OFF_T3   = OFF_T2   + (size_t)TTOK*DM;
constexpr size_t OFF_WCOMB= OFF_T3   + (size_t)TTOK*DM;        // [4,544,512]
constexpr size_t OFF_MEAN = OFF_WCOMB+ (size_t)4*544*512;
constexpr size_t OFF_STD  = OFF_MEAN + (size_t)BATCH*NVARS;
constexpr size_t OFF_P    = OFF_STD  + (size_t)BATCH*NVARS;
constexpr size_t OFF_HL   = OFF_P    + NSTATE;
constexpr size_t OFF_HI   = OFF_HL   + NSTATE;
constexpr size_t SCRATCH_FLOATS = OFF_HI + NSTATE;

__device__ float g_scratch[SCRATCH_FLOATS];

// ================= bf16-split tensor-core GEMM =============================
// C[M,N] = act(A[M,K(lda)] * W[N,K]^T + bias), 3-product bf16 split.
enum { ACT_NONE = 0, ACT_RELU = 1, ACT_DELTABC = 2, ACT_GATE = 3 };

#define BM 128
#define BN 128
#define BKF 32
#define LPITCH 36                   // u32 per smem row (hi[32] lo[32] pad)
#define ROWB 144
#define TILE_BYTES (128*ROWB)       // 18432
#define STAGE_BYTES (2*TILE_BYTES)  // 36864
#define SMEM_GEMM (2*STAGE_BYTES)   // 73728

__device__ __forceinline__ uint32_t smem_u32(const void* p) {
    uint32_t a;
    asm("{ .reg .u64 t; cvta.to.shared.u64 t, %1; cvt.u32.u64 %0, t; }"
        : "=r"(a) : "l"(p));
    return a;
}

__device__ __forceinline__ uint32_t pack_bf16(float a, float b) {
    __nv_bfloat162 t = __floats2bfloat162_rn(a, b);
    return *reinterpret_cast<uint32_t*>(&t);
}

#define LDSM_X4(r0,r1,r2,r3,addr) \
    asm volatile("ldmatrix.sync.aligned.m8n8.x4.shared.b16 {%0,%1,%2,%3}, [%4];" \
        : "=r"(r0),"=r"(r1),"=r"(r2),"=r"(r3) : "r"(addr))

#define MMA_BF16(d,a,b0,b1) \
    asm volatile("mma.sync.aligned.m16n8k16.row.col.f32.bf16.bf16.f32 " \
        "{%0,%1,%2,%3}, {%4,%5,%6,%7}, {%8,%9}, {%0,%1,%2,%3};" \
        : "+f"((d)[0]),"+f"((d)[1]),"+f"((d)[2]),"+f"((d)[3]) \
        : "r"((a)[0]),"r"((a)[1]),"r"((a)[2]),"r"((a)[3]), "r"(b0),"r"(b1))

template <int ACT>
__global__ void __launch_bounds__(512, 1)
mma_gemm(const float* __restrict__ A, int lda,
         const float* __restrict__ W,
         const float* __restrict__ bias,
         float* __restrict__ C, int ldc,
         int M, int N, int K,
         const float* __restrict__ e1, const float* __restrict__ e2,
         size_t zsA, size_t zsW, size_t zsC, size_t zsBias)
{
    extern __shared__ char smem[];
    const uint32_t sbase = smem_u32(smem);
    const int tid  = threadIdx.x;
    const int lane = tid & 31;
    const int wid  = tid >> 5;          // 16 warps
    const int warp_m = wid & 3;         // 4 x 32 rows
    const int warp_n = wid >> 2;        // 4 x 32 cols
    const int bm = blockIdx.y * BM, bn = blockIdx.x * BN;

    A += blockIdx.z * zsA;
    W += blockIdx.z * zsW;
    C += blockIdx.z * zsC;
    if (bias) bias += blockIdx.z * zsBias;

    const int c4 = tid & 7;             // float4 index within 32-float row
    const int r0g = tid >> 3;           // base row (0..63), +64*i

    float4 aReg[2], bReg[2];

    auto load_global = [&](int kt) {
        const float* Ap = A + (size_t)kt * BKF + (size_t)c4 * 4;
        const float* Wp = W + (size_t)kt * BKF + (size_t)c4 * 4;
#pragma unroll
        for (int i = 0; i < 2; i++) {
            int row = r0g + i * 64;
            int gr = bm + row;
            aReg[i] = (gr < M) ? *reinterpret_cast<const float4*>(Ap + (size_t)gr * lda)
                               : make_float4(0.f, 0.f, 0.f, 0.f);
            int gn = bn + row;
            bReg[i] = (gn < N) ? *reinterpret_cast<const float4*>(Wp + (size_t)gn * K)
                               : make_float4(0.f, 0.f, 0.f, 0.f);
        }
    };

    auto store_stage = [&](int s) {
        uint32_t* sa = reinterpret_cast<uint32_t*>(smem + s * STAGE_BYTES);
        uint32_t* sb = reinterpret_cast<uint32_t*>(smem + s * STAGE_BYTES + TILE_BYTES);
#pragma unroll
        for (int i = 0; i < 2; i++) {
            int row = r0g + i * 64;
            {
                float4 v = aReg[i];
                float hx = __bfloat162float(__float2bfloat16_rn(v.x));
                float hy = __bfloat162float(__float2bfloat16_rn(v.y));
                float hz = __bfloat162float(__float2bfloat16_rn(v.z));
                float hw = __bfloat162float(__float2bfloat16_rn(v.w));
                uint32_t* p = sa + row * LPITCH + c4 * 2;
                p[0] = pack_bf16(hx, hy);
                p[1] = pack_bf16(hz, hw);
                p[16] = pack_bf16(v.x - hx, v.y - hy);
                p[17] = pack_bf16(v.z - hz, v.w - hw);
            }
            {
                float4 v = bReg[i];
                float hx = __bfloat162float(__float2bfloat16_rn(v.x));
                float hy = __bfloat162float(__float2bfloat16_rn(v.y));
                float hz = __bfloat162float(__float2bfloat16_rn(v.z));
                float hw = __bfloat162float(__float2bfloat16_rn(v.w));
                uint32_t* p = sb + row * LPITCH + c4 * 2;
                p[0] = pack_bf16(hx, hy);
                p[1] = pack_bf16(hz, hw);
                p[16] = pack_bf16(v.x - hx, v.y - hy);
                p[17] = pack_bf16(v.z - hz, v.w - hw);
            }
        }
    };

    const uint32_t a_off = (uint32_t)(warp_m * 32 + (lane & 15)) * ROWB + ((lane >> 4) * 16);
    const uint32_t b_off = (uint32_t)(warp_n * 32 + ((lane >> 4) & 1) * 8 + (lane & 7)) * ROWB
                         + (((lane >> 3) & 1) * 16);

    float acc[2][4][4];
#pragma unroll
    for (int i = 0; i < 2; i++)
#pragma unroll
        for (int j = 0; j < 4; j++)
#pragma unroll
            for (int e = 0; e < 4; e++) acc[i][j][e] = 0.f;

    const int KT = K / BKF;
    load_global(0);
    store_stage(0);
    __syncthreads();

    for (int kt = 0; kt < KT; kt++) {
        if (kt + 1 < KT) load_global(kt + 1);
        const uint32_t Ab = sbase + (kt & 1) * STAGE_BYTES;
        const uint32_t Bb = Ab + TILE_BYTES;
        // products: hi*hi (ks 0,1) ; lo*hi (ks 2,3) ; hi*lo (ks 4,5)
#pragma unroll
        for (int ks = 0; ks < 6; ks++) {
            const int kk = ks & 1;
            const int segA = (ks == 2 || ks == 3) ? 1 : 0;
            const int segB = (ks >= 4) ? 1 : 0;
            const uint32_t ao = Ab + a_off + segA * 64 + kk * 32;
            const uint32_t bo = Bb + b_off + segB * 64 + kk * 32;
            uint32_t a[2][4];
#pragma unroll
            for (int mt = 0; mt < 2; mt++)
                LDSM_X4(a[mt][0], a[mt][1], a[mt][2], a[mt][3], ao + mt * 16 * ROWB);
            uint32_t b[2][4];
#pragma unroll
            for (int p = 0; p < 2; p++)
                LDSM_X4(b[p][0], b[p][1], b[p][2], b[p][3], bo + p * 16 * ROWB);
#pragma unroll
            for (int mt = 0; mt < 2; mt++) {
                MMA_BF16(acc[mt][0], a[mt], b[0][0], b[0][1]);
                MMA_BF16(acc[mt][1], a[mt], b[0][2], b[0][3]);
                MMA_BF16(acc[mt][2], a[mt], b[1][0], b[1][1]);
                MMA_BF16(acc[mt][3], a[mt], b[1][2], b[1][3]);
            }
        }
        if (kt + 1 < KT) store_stage((kt + 1) & 1);
        __syncthreads();
    }

    // ---- epilogue ----
    const int er = bm + warp_m * 32 + (lane >> 2);
    const int ec = bn + warp_n * 32 + (lane & 3) * 2;
#pragma unroll
    for (int mt = 0; mt < 2; mt++) {
#pragma unroll
        for (int nt = 0; nt < 4; nt++) {
            int gc = ec + nt * 8;
            if (gc >= N) continue;
            float b0 = 0.f, b1 = 0.f;
            if (bias) {
                if (ACT == ACT_DELTABC) {
                    if (gc < 512)     b0 = bias[gc];
                    if (gc + 1 < 512) b1 = bias[gc + 1];
                } else {
                    b0 = bias[gc]; b1 = bias[gc + 1];
                }
            }
#pragma unroll
            for (int h = 0; h < 2; h++) {
                int gr = er + mt * 16 + h * 8;
                if (gr >= M) continue;
                float v0 = acc[mt][nt][h * 2 + 0];
                float v1 = acc[mt][nt][h * 2 + 1];
                if (ACT == ACT_NONE) {
                    v0 += b0; v1 += b1;
                    *reinterpret_cast<float2*>(&C[(size_t)gr * ldc + gc]) =
                        make_float2(v0, v1);
                } else if (ACT == ACT_RELU) {
                    v0 = fmaxf(v0 + b0, 0.f); v1 = fmaxf(v1 + b1, 0.f);
                    *reinterpret_cast<float2*>(&C[(size_t)gr * ldc + gc]) =
                        make_float2(v0, v1);
                } else if (ACT == ACT_DELTABC) {
                    // C = dx buffer (ldc=2048, z offset applied), delta at col 2*gc
                    // e1 = bc buffer [T,64] (B,C) interleaved
                    float* bco = const_cast<float*>(e1) + blockIdx.z * 32;
                    if (gc < 512) {
                        v0 += b0; v1 += b1;
                        v0 = fmaxf(v0, 0.f) + log1pf(__expf(-fabsf(v0)));
                        v1 = fmaxf(v1, 0.f) + log1pf(__expf(-fabsf(v1)));
                        C[(size_t)gr * 2048 + 2 * gc]     = v0;
                        C[(size_t)gr * 2048 + 2 * gc + 2] = v1;
                    } else if (gc < 528) {
                        int s = gc - 512;
                        bco[(size_t)gr * 64 + 2 * s]     = v0;   // B_s
                        bco[(size_t)gr * 64 + 2 * s + 2] = v1;   // B_{s+1}
                    } else if (gc < 544) {
                        int s = gc - 528;
                        bco[(size_t)gr * 64 + 2 * s + 1] = v0;   // C_s
                        bco[(size_t)gr * 64 + 2 * s + 3] = v1;   // C_{s+1}
                    }
                } else if (ACT == ACT_GATE) {
                    size_t ix = (size_t)gr * ldc + gc;
                    float s0 = 1.f / (1.f + __expf(-(v0 + b0)));
                    float s1 = 1.f / (1.f + __expf(-(v1 + b1)));
                    v0 = e1[ix] + s0 * e2[ix];
                    v1 = e1[ix + 1] + s1 * e2[ix + 1];
                    *reinterpret_cast<float2*>(&C[ix]) = make_float2(v0, v1);
                }
            }
        }
    }
}

// ================= small kernels ==========================================
__global__ void stats_kernel(const float* __restrict__ x_enc,
                             float* __restrict__ means, float* __restrict__ stds)
{
    int idx = blockIdx.x * blockDim.x + threadIdx.x;
    if (idx >= BATCH * NVARS) return;
    int b = idx / NVARS, n = idx - b * NVARS;
    float s = 0.f, sq = 0.f;
    for (int t = 0; t < SEQ; t++) {
        float v = x_enc[((size_t)b * SEQ + t) * NVARS + n];
        s += v; sq += v * v;
    }
    float m = s * (1.f / SEQ);
    float var = sq * (1.f / SEQ) - m * m;
    means[idx] = m;
    stds[idx] = sqrtf(var + 1e-5f);
}

__global__ void tok_kernel(const float* __restrict__ x_enc,
                           const float* __restrict__ x_mark,
                           const float* __restrict__ means,
                           const float* __restrict__ stds,
                           float* __restrict__ tok)
{
    int idx = blockIdx.x * blockDim.x + threadIdx.x;
    if (idx >= TTOK * SEQ) return;
    int sIdx = idx % SEQ;
    int t = idx / SEQ;
    int b = t / LTOK, v = t - b * LTOK;
    float val;
    if (v < NVARS) {
        val = (x_enc[((size_t)b * SEQ + sIdx) * NVARS + v] - means[b * NVARS + v])
              / stds[b * NVARS + v];
    } else {
        val = x_mark[((size_t)b * SEQ + sIdx) * NMARK + (v - NVARS)];
    }
    tok[idx] = val;
}

// W_comb[w][n][k]: n<512 -> sum_r dtw[w,n,r]*xpw[w,r,k];  n>=512 -> xpw[w,32+n-512,k]
__global__ void wcomb_kernel(const float* __restrict__ dtw,
                             const float* __restrict__ xpw,
                             float* __restrict__ wcomb)
{
    int idx = blockIdx.x * blockDim.x + threadIdx.x;
    if (idx >= 4 * 544 * 512) return;
    int w = idx / (544 * 512);
    int rem = idx - w * 544 * 512;
    int n = rem >> 9;
    int k = rem & 511;
    float v;
    if (n < 512) {
        const float* dr = dtw + ((size_t)w * 512 + n) * 32;
        const float* xr = xpw + (size_t)w * 64 * 512 + k;
        v = 0.f;
#pragma unroll
        for (int r = 0; r < 32; r++) v = fmaf(dr[r], xr[(size_t)r * 512], v);
    } else {
        v = xpw[(size_t)w * 64 * 512 + (size_t)(32 + n - 512) * 512 + k];
    }
    wcomb[idx] = v;
}

// depthwise conv(2) + SiLU, both dirs. xzB: [T,2048] = [xi0|z0|xi1|z1]
// writes xc (contiguous, per dir) AND dx pair slot [t][dir*1024 + 2d+1]
__global__ void conv_silu_kernel(const float* __restrict__ xzB,
                                 const float* __restrict__ cw,   // [2,DM,2]
                                 const float* __restrict__ cb,   // [2,DM]
                                 float* __restrict__ xc0, float* __restrict__ xc1,
                                 float* __restrict__ dx)
{
    int idx = blockIdx.x * blockDim.x + threadIdx.x;
    const int n = TTOK * DM;
    if (idx >= 2 * n) return;
    int dir = idx >= n;
    int r = idx - dir * n;
    int d = r & (DM - 1);
    int t = r >> 9;
    int b = t / LTOK, l = t - b * LTOK;
    const float* base = xzB + (size_t)dir * 1024;
    float cur = base[(size_t)t * 2048 + d];
    int ln = dir ? (l + 1) : (l - 1);
    float nb = 0.f;
    if (ln >= 0 && ln < LTOK)
        nb = base[(size_t)(t + (dir ? 1 : -1)) * 2048 + d];
    float w0 = cw[(size_t)dir * DM * 2 + d * 2 + 0];
    float w1 = cw[(size_t)dir * DM * 2 + d * 2 + 1];
    float v = w0 * nb + w1 * cur + cb[dir * DM + d];
    float out = v / (1.f + __expf(-v));
    (dir ? xc1 : xc0)[r] = out;
    dx[(size_t)t * 2048 + dir * 1024 + 2 * d + 1] = out;
}

// ---------------- chunked selective scan (warp=32 d, states in regs) -------
// warp w = dir*4096 + b*512 + dblk*32 + ch ; lane = d within 32-block.
__global__ void __launch_bounds__(256)
scan_p1(const float* __restrict__ dx, const float* __restrict__ bcb,
        const float* __restrict__ A_log_l,   // [2,DM,DS]
        float* __restrict__ P, float* __restrict__ H)
{
    int w = blockIdx.x * 8 + (threadIdx.x >> 5);
    int lane = threadIdx.x & 31;
    int ch = w & 31;
    int dblk = (w >> 5) & 15;
    int b = (w >> 9) & 7;
    int dir = w >> 12;
    int d = dblk * 32 + lane;

    float a[DS];
#pragma unroll
    for (int s = 0; s < DS; s++)
        a[s] = -__expf(A_log_l[((size_t)dir * DM + d) * DS + s]) * 1.44269504f;

    float h[DS], Pr[DS];
#pragma unroll
    for (int s = 0; s < DS; s++) { h[s] = 0.f; Pr[s] = 1.f; }

    int i0 = ch * CHL;
    int nn = LTOK - i0; if (nn > CHL) nn = CHL; if (nn < 0) nn = 0;
    int l0 = dir ? (LTOK - 1 - i0) : i0;
    long t0 = (long)b * LTOK + l0;
    long stp = dir ? -1 : 1;
    const float2* dxp = (const float2*)dx + t0 * 1024 + dir * 512 + d;
    const float2* bp  = (const float2*)bcb + t0 * 32 + dir * 16;
    long sdx = stp * 1024, sbc = stp * 32;

    for (int i = 0; i < nn; i++) {
        float2 dv = *dxp;
        float u = dv.x * dv.y;           // dlt * x
#pragma unroll
        for (int s = 0; s < DS; s++) {
            float2 bcv = bp[s];
            float dA = exp2f(dv.x * a[s]);
            Pr[s] *= dA;
            h[s] = fmaf(dA, h[s], bcv.x * u);
        }
        dxp += sdx; bp += sbc;
    }
    float* Po = P + ((size_t)w * 32 + lane) * 16;
    float* Ho = H + ((size_t)w * 32 + lane) * 16;
#pragma unroll
    for (int s = 0; s < DS; s++) { Po[s] = Pr[s]; Ho[s] = h[s]; }
}

// Combine: serial over 32 chunks per (dir,b,d,s) -> per-chunk init states.
__global__ void scan_comb(const float* __restrict__ P,
                          const float* __restrict__ Hl,
                          float* __restrict__ Hin)
{
    int idx = blockIdx.x * blockDim.x + threadIdx.x;   // (dir,b,dblk,lane,s)
    if (idx >= 2 * BATCH * DM * 16) return;
    int s = idx & 15;
    int lane = (idx >> 4) & 31;
    int dblk = (idx >> 9) & 15;
    int b = (idx >> 13) & 7;
    int dir = idx >> 16;
    size_t w0 = (size_t)dir * 4096 + (size_t)b * 512 + (size_t)dblk * 32;
    float h = 0.f;
#pragma unroll
    for (int ch = 0; ch < NCH; ch++) {
        size_t o = ((w0 + ch) * 32 + lane) * 16 + s;
        Hin[o] = h;
        h = P[o] * h + Hl[o];
    }
}

// Pass 2: re-scan each chunk from Hin, producing gated outputs.
__global__ void __launch_bounds__(256)
scan_p2(const float* __restrict__ dx, const float* __restrict__ bcb,
        const float* __restrict__ xzB,
        const float* __restrict__ A_log_l,   // [2,DM,DS]
        const float* __restrict__ Dp_l,      // [2,DM]
        const float* __restrict__ Hin,
        float* __restrict__ yp0, float* __restrict__ yp1)
{
    int w = blockIdx.x * 8 + (threadIdx.x >> 5);
    int lane = threadIdx.x & 31;
    int ch = w & 31;
    int dblk = (w >> 5) & 15;
    int b = (w >> 9) & 7;
    int dir = w >> 12;
    int d = dblk * 32 + lane;

    float a[DS];
#pragma unroll
    for (int s = 0; s < DS; s++)
        a[s] = -__expf(A_log_l[((size_t)dir * DM + d) * DS + s]) * 1.44269504f;
    float Dv = Dp_l[dir * DM + d];

    float h[DS];
    const float* Hi = Hin + ((size_t)w * 32 + lane) * 16;
#pragma unroll
    for (int s = 0; s < DS; s++) h[s] = Hi[s];

    int i0 = ch * CHL;
    int nn = LTOK - i0; if (nn > CHL) nn = CHL; if (nn < 0) nn = 0;
    int l0 = dir ? (LTOK - 1 - i0) : i0;
    long t0 = (long)b * LTOK + l0;
    long stp = dir ? -1 : 1;
    const float2* dxp = (const float2*)dx + t0 * 1024 + dir * 512 + d;
    const float2* bp  = (const float2*)bcb + t0 * 32 + dir * 16;
    const float*  zp  = xzB + t0 * 2048 + dir * 1024 + 512 + d;
    float* ypp = (dir ? yp1 : yp0) + t0 * 512 + d;
    long sdx = stp * 1024, sbc = stp * 32, sz = stp * 2048, sy = stp * 512;

    for (int i = 0; i < nn; i++) {
        float2 dv = *dxp;
        float u = dv.x * dv.y;
        float y0 = 0.f, y1 = 0.f, y2 = 0.f, y3 = 0.f;
#pragma unroll
        for (int s = 0; s < DS; s++) {
            float2 bcv = bp[s];
            float dA = exp2f(dv.x * a[s]);
            h[s] = fmaf(dA, h[s], bcv.x * u);
            float t = h[s] * bcv.y;
            if ((s & 3) == 0) y0 += t;
            else if ((s & 3) == 1) y1 += t;
            else if ((s & 3) == 2) y2 += t;
            else y3 += t;
        }
        float y = (y0 + y1) + (y2 + y3);
        float z = *zp;
        float szl = z / (1.f + __expf(-z));
        *ypp = (y + Dv * dv.y) * szl;
        dxp += sdx; bp += sbc; zp += sz; ypp += sy;
    }
}

__global__ void ln_kernel(const float* __restrict__ i1,
                          const float* __restrict__ i2,
                          const float* __restrict__ i3,
                          const float* __restrict__ g,
                          const float* __restrict__ bta,
                          float* __restrict__ out)
{
    int row = blockIdx.x * (blockDim.x >> 5) + (threadIdx.x >> 5);
    int lane = threadIdx.x & 31;
    if (row >= TTOK) return;
    size_t rb = (size_t)row * DM;
    float vals[16];
    float s = 0.f, sq = 0.f;
#pragma unroll
    for (int i = 0; i < 16; i++) {
        int c = lane + i * 32;
        float v = i1[rb + c];
        if (i2) v += i2[rb + c];
        if (i3) v += i3[rb + c];
        vals[i] = v; s += v; sq += v * v;
    }
#pragma unroll
    for (int o = 16; o; o >>= 1) {
        s  += __shfl_xor_sync(0xffffffffu, s, o);
        sq += __shfl_xor_sync(0xffffffffu, sq, o);
    }
    float m = s * (1.f / DM);
    float var = sq * (1.f / DM) - m * m;
    float r = rsqrtf(var + 1e-5f);
#pragma unroll
    for (int i = 0; i < 16; i++) {
        int c = lane + i * 32;
        out[rb + c] = (vals[i] - m) * r * g[c] + bta[c];
    }
}

__global__ void out_kernel(const float* __restrict__ dec,
                           const float* __restrict__ means,
                           const float* __restrict__ stds,
                           float* __restrict__ out)
{
    int idx = blockIdx.x * blockDim.x + threadIdx.x;
    if (idx >= BATCH * PRED * NVARS) return;
    int b = idx / (PRED * NVARS);
    int rem = idx - b * (PRED * NVARS);
    int p = rem / NVARS;
    int n = rem - p * NVARS;
    float v = dec[((size_t)b * LTOK + n) * PRED + p];
    out[idx] = v * stds[b * NVARS + n] + means[b * NVARS + n];
}

// ================= host orchestration ======================================
template <int ACT>
static void launch_mma(const float* A, int lda, const float* W, const float* bias,
                       float* C, int ldc, int M, int N, int K,
                       const float* e1 = nullptr, const float* e2 = nullptr,
                       int Z = 1, size_t zsA = 0, size_t zsW = 0,
                       size_t zsC = 0, size_t zsBias = 0)
{
    dim3 grid(CDIV(N, BN), CDIV(M, BM), Z);
    mma_gemm<ACT><<<grid, 512, SMEM_GEMM>>>(A, lda, W, bias, C, ldc, M, N, K,
                                            e1, e2, zsA, zsW, zsC, zsBias);
}

extern "C" void kernel_launch(void* const* d_in, const int* in_sizes, int n_in,
                              void* d_out, int out_size)
{
    const float* x_enc    = (const float*)d_in[0];
    const float* x_mark   = (const float*)d_in[1];
    const float* emb_w    = (const float*)d_in[4];
    const float* emb_b    = (const float*)d_in[5];
    const float* in_proj  = (const float*)d_in[6];
    const float* conv_w   = (const float*)d_in[7];
    const float* conv_b   = (const float*)d_in[8];
    const float* x_proj   = (const float*)d_in[9];
    const float* dt_w     = (const float*)d_in[10];
    const float* dt_b     = (const float*)d_in[11];
    const float* A_log    = (const float*)d_in[12];
    const float* D_param  = (const float*)d_in[13];
    const float* out_w    = (const float*)d_in[14];
    const float* ffn_w1   = (const float*)d_in[15];
    const float* ffn_b1   = (const float*)d_in[16];
    const float* ffn_w2   = (const float*)d_in[17];
    const float* ffn_b2   = (const float*)d_in[18];
    const float* ln1_g    = (const float*)d_in[19];
    const float* ln1_b    = (const float*)d_in[20];
    const float* ln2_g    = (const float*)d_in[21];
    const float* ln2_b    = (const float*)d_in[22];
    const float* fin_g    = (const float*)d_in[23];
    const float* fin_b    = (const float*)d_in[24];
    const float* gate_w   = (const float*)d_in[25];
    const float* gate_b   = (const float*)d_in[26];
    const float* proj_w   = (const float*)d_in[27];
    const float* proj_b   = (const float*)d_in[28];

    cudaFuncSetAttribute(mma_gemm<ACT_NONE>,    cudaFuncAttributeMaxDynamicSharedMemorySize, SMEM_GEMM);
    cudaFuncSetAttribute(mma_gemm<ACT_RELU>,    cudaFuncAttributeMaxDynamicSharedMemorySize, SMEM_GEMM);
    cudaFuncSetAttribute(mma_gemm<ACT_DELTABC>, cudaFuncAttributeMaxDynamicSharedMemorySize, SMEM_GEMM);
    cudaFuncSetAttribute(mma_gemm<ACT_GATE>,    cudaFuncAttributeMaxDynamicSharedMemorySize, SMEM_GEMM);

    float* S = nullptr;
    cudaGetSymbolAddress((void**)&S, g_scratch);

    float* tok   = S + OFF_TOK;
    float* dec   = S + OFF_DEC;
    float* enc   = S + OFF_ENC;
    float* raw   = S + OFF_RAW;
    float* xzB   = S + OFF_XZB;
    float* xcb[2] = { S + OFF_XC0,  S + OFF_XC1 };
    float* dx    = S + OFF_DX;
    float* bcb   = S + OFF_BC;
    float* yp[2]  = { S + OFF_YP0,  S + OFF_YP1 };
    float* mo[2]  = { S + OFF_MO0,  S + OFF_MO1 };
    float* t1    = S + OFF_T1;
    float* t2    = S + OFF_T2;
    float* t3    = S + OFF_T3;
    float* wcomb = S + OFF_WCOMB;
    float* means = S + OFF_MEAN;
    float* stds  = S + OFF_STD;
    float* Pbuf  = S + OFF_P;
    float* Hlbuf = S + OFF_HL;
    float* Hibuf = S + OFF_HI;

    stats_kernel<<<CDIV(BATCH * NVARS, 256), 256>>>(x_enc, means, stds);
    tok_kernel<<<CDIV(TTOK * SEQ, 256), 256>>>(x_enc, x_mark, means, stds, tok);
    wcomb_kernel<<<CDIV(4 * 544 * 512, 256), 256>>>(dt_w, x_proj, wcomb);

    // embedding GEMM -> enc
    launch_mma<ACT_NONE>(tok, SEQ, emb_w, emb_b, enc, DM, TTOK, DM, SEQ);
    cudaMemcpyAsync(raw, enc, (size_t)TTOK * DM * sizeof(float),
                    cudaMemcpyDeviceToDevice);

    for (int l = 0; l < NL; l++) {
        // merged fwd+rev in_proj: N=2048
        launch_mma<ACT_NONE>(enc, DM, in_proj + (size_t)l * 2 * 2 * DM * DM,
                             nullptr, xzB, 4 * DM, TTOK, 4 * DM, DM);
        conv_silu_kernel<<<CDIV(2 * TTOK * DM, 256), 256>>>(
            xzB, conv_w + (size_t)l * 2 * DM * 2, conv_b + (size_t)l * 2 * DM,
            xcb[0], xcb[1], dx);

        // fused delta(softplus)+B+C GEMM, both dirs (z=2) -> dx / bcb
        launch_mma<ACT_DELTABC>(xcb[0], DM, wcomb + (size_t)l * 2 * 544 * 512,
                                dt_b + (size_t)l * 2 * DM, dx, 2048,
                                TTOK, 544, DM, bcb, nullptr,
                                2, (size_t)TTOK * DM, (size_t)544 * 512,
                                1024, DM);

        // chunked scan
        scan_p1<<<NWARP / 8, 256>>>(dx, bcb,
                                    A_log + (size_t)l * 2 * DM * DS,
                                    Pbuf, Hlbuf);
        scan_comb<<<CDIV(2 * BATCH * DM * 16, 256), 256>>>(Pbuf, Hlbuf, Hibuf);
        scan_p2<<<NWARP / 8, 256>>>(dx, bcb, xzB,
                                    A_log + (size_t)l * 2 * DM * DS,
                                    D_param + (size_t)l * 2 * DM,
                                    Hibuf, yp[0], yp[1]);

        // out projection, both dirs (z=2)
        launch_mma<ACT_NONE>(yp[0], DM, out_w + (size_t)l * 2 * DM * DM,
                             nullptr, mo[0], DM, TTOK, DM, DM, nullptr, nullptr,
                             2, (size_t)TTOK * DM, (size_t)DM * DM,
                             (size_t)TTOK * DM, 0);

        ln_kernel<<<CDIV(TTOK, 8), 256>>>(enc, mo[0], mo[1],
                                          ln1_g + l * DM, ln1_b + l * DM, t1);
        launch_mma<ACT_RELU>(t1, DM, ffn_w1 + (size_t)l * DFF * DM,
                             ffn_b1 + l * DFF, t2, DFF, TTOK, DFF, DM);
        launch_mma<ACT_NONE>(t2, DFF, ffn_w2 + (size_t)l * DM * DFF,
                             ffn_b2 + l * DM, t3, DM, TTOK, DM, DFF);
        ln_kernel<<<CDIV(TTOK, 8), 256>>>(t1, t3, nullptr,
                                          ln2_g + l * DM, ln2_b + l * DM, enc);
    }

    ln_kernel<<<CDIV(TTOK, 8), 256>>>(enc, nullptr, nullptr, fin_g, fin_b, t2);
    launch_mma<ACT_GATE>(raw, DM, gate_w, gate_b, t1, DM, TTOK, DM, DM, t2, raw);
    launch_mma<ACT_NONE>(t1, DM, proj_w, proj_b, dec, PRED, TTOK, PRED, DM);
    out_kernel<<<CDIV(BATCH * PRED * NVARS, 256), 256>>>(dec, means, stds,
                                                         (float*)d_out);
}

// round 6
// speedup vs baseline: 3.8066x; 1.1937x over previous
#include <cuda_runtime.h>
#include <cuda_bf16.h>
#include <math.h>
#include <stdint.h>

// ---------------- problem constants ----------------
#define BATCH 8
#define SEQ   96
#define PRED  96
#define NVARS 862
#define NMARK 4
#define LTOK  866
#define TTOK  (BATCH*LTOK)   // 6928
#define DM    512
#define DS    16
#define DFF   512
#define RK    32
#define NL    2

// chunked scan: warp = 32 d-channels, 16 states/lane in registers
#define NCH   32
#define CHL   28             // 32*28 = 896 >= 866
#define NWARP (2*BATCH*16*NCH)          // 8192 warps (dir,b,dblk,ch)
#define NSTATE ((size_t)NWARP*32*16)

#define CDIV(a,b) (((a)+(b)-1)/(b))

// ================= scratch (static; no allocs) =============================
constexpr size_t OFF_TOK  = 0;
constexpr size_t OFF_DEC  = OFF_TOK  + (size_t)TTOK*96;
constexpr size_t OFF_ENC  = OFF_DEC  + (size_t)TTOK*96;
constexpr size_t OFF_RAW  = OFF_ENC  + (size_t)TTOK*DM;
constexpr size_t OFF_XZB  = OFF_RAW  + (size_t)TTOK*DM;        // [T, 2048]
constexpr size_t OFF_XC0  = OFF_XZB  + (size_t)TTOK*4*DM;
constexpr size_t OFF_XC1  = OFF_XC0  + (size_t)TTOK*DM;
constexpr size_t OFF_DX   = OFF_XC1  + (size_t)TTOK*DM;        // [T,2048] (dlt,x)
constexpr size_t OFF_BC   = OFF_DX   + (size_t)TTOK*2048;      // [T,64] (B,C)
constexpr size_t OFF_YP0  = OFF_BC   + (size_t)TTOK*64;
constexpr size_t OFF_YP1  = OFF_YP0  + (size_t)TTOK*DM;
constexpr size_t OFF_MO0  = OFF_YP1  + (size_t)TTOK*DM;
constexpr size_t OFF_MO1  = OFF_MO0  + (size_t)TTOK*DM;
constexpr size_t OFF_T1   = OFF_MO1  + (size_t)TTOK*DM;
constexpr size_t OFF_T2   = OFF_T1   + (size_t)TTOK*DM;
constexpr size_t OFF_T3   = OFF_T2   + (size_t)TTOK*DM;
constexpr size_t OFF_WCOMB= OFF_T3   + (size_t)TTOK*DM;        // [4,544,512]
constexpr size_t OFF_MEAN = OFF_WCOMB+ (size_t)4*544*512;
constexpr size_t OFF_STD  = OFF_MEAN + (size_t)BATCH*NVARS;
constexpr size_t OFF_P    = OFF_STD  + (size_t)BATCH*NVARS;
constexpr size_t OFF_HL   = OFF_P    + NSTATE;
constexpr size_t OFF_HI   = OFF_HL   + NSTATE;
constexpr size_t SCRATCH_FLOATS = OFF_HI + NSTATE;

__device__ float g_scratch[SCRATCH_FLOATS];

// ================= bf16-split tensor-core GEMM =============================
// C[M,N] = act(A[M,K(lda)] * W[N,K]^T + bias), 3-product bf16 split.
// BM=64 / BN=128 / 256 threads / 2 CTAs per SM.
enum { ACT_NONE = 0, ACT_RELU = 1, ACT_DELTABC = 2, ACT_GATE = 3, ACT_DUP = 4 };

#define BM 64
#define BN 128
#define BKF 32
#define LPITCH 36                   // u32 per smem row (hi[32] lo[32] pad)
#define ROWB 144
#define A_TILE_B (64*ROWB)          // 9216
#define B_TILE_B (128*ROWB)         // 18432
#define STAGE_B  (A_TILE_B + B_TILE_B)  // 27648
#define SMEM_GEMM (2*STAGE_B)       // 55296

__device__ __forceinline__ uint32_t smem_u32(const void* p) {
    uint32_t a;
    asm("{ .reg .u64 t; cvta.to.shared.u64 t, %1; cvt.u32.u64 %0, t; }"
        : "=r"(a) : "l"(p));
    return a;
}

__device__ __forceinline__ uint32_t pack_bf16(float a, float b) {
    __nv_bfloat162 t = __floats2bfloat162_rn(a, b);
    return *reinterpret_cast<uint32_t*>(&t);
}

#define LDSM_X4(r0,r1,r2,r3,addr) \
    asm volatile("ldmatrix.sync.aligned.m8n8.x4.shared.b16 {%0,%1,%2,%3}, [%4];" \
        : "=r"(r0),"=r"(r1),"=r"(r2),"=r"(r3) : "r"(addr))

#define MMA_BF16(d,a,b0,b1) \
    asm volatile("mma.sync.aligned.m16n8k16.row.col.f32.bf16.bf16.f32 " \
        "{%0,%1,%2,%3}, {%4,%5,%6,%7}, {%8,%9}, {%0,%1,%2,%3};" \
        : "+f"((d)[0]),"+f"((d)[1]),"+f"((d)[2]),"+f"((d)[3]) \
        : "r"((a)[0]),"r"((a)[1]),"r"((a)[2]),"r"((a)[3]), "r"(b0),"r"(b1))

template <int ACT>
__global__ void __launch_bounds__(256, 2)
mma_gemm(const float* __restrict__ A, int lda,
         const float* __restrict__ W,
         const float* __restrict__ bias,
         float* __restrict__ C, int ldc,
         int M, int N, int K,
         const float* __restrict__ e1, const float* __restrict__ e2,
         size_t zsA, size_t zsW, size_t zsC, size_t zsBias)
{
    extern __shared__ char smem[];
    const uint32_t sbase = smem_u32(smem);
    const int tid  = threadIdx.x;
    const int lane = tid & 31;
    const int wid  = tid >> 5;          // 8 warps
    const int warp_m = wid & 1;         // 2 x 32 rows
    const int warp_n = wid >> 1;        // 4 x 32 cols
    const int bm = blockIdx.y * BM, bn = blockIdx.x * BN;

    A += blockIdx.z * zsA;
    W += blockIdx.z * zsW;
    C += blockIdx.z * zsC;
    if (bias) bias += blockIdx.z * zsBias;

    const int c4 = tid & 7;             // float4 index within 32-float row
    const int r0g = tid >> 3;           // base row (0..31)

    float4 aReg[2], bReg[4];

    auto load_global = [&](int kt) {
        const float* Ap = A + (size_t)kt * BKF + (size_t)c4 * 4;
        const float* Wp = W + (size_t)kt * BKF + (size_t)c4 * 4;
#pragma unroll
        for (int i = 0; i < 2; i++) {
            int gr = bm + r0g + i * 32;
            aReg[i] = (gr < M) ? *reinterpret_cast<const float4*>(Ap + (size_t)gr * lda)
                               : make_float4(0.f, 0.f, 0.f, 0.f);
        }
#pragma unroll
        for (int i = 0; i < 4; i++) {
            int gn = bn + r0g + i * 32;
            bReg[i] = (gn < N) ? *reinterpret_cast<const float4*>(Wp + (size_t)gn * K)
                               : make_float4(0.f, 0.f, 0.f, 0.f);
        }
    };

    auto store_stage = [&](int s) {
        uint32_t* sa = reinterpret_cast<uint32_t*>(smem + s * STAGE_B);
        uint32_t* sb = reinterpret_cast<uint32_t*>(smem + s * STAGE_B + A_TILE_B);
#pragma unroll
        for (int i = 0; i < 2; i++) {
            int row = r0g + i * 32;
            float4 v = aReg[i];
            float hx = __bfloat162float(__float2bfloat16_rn(v.x));
            float hy = __bfloat162float(__float2bfloat16_rn(v.y));
            float hz = __bfloat162float(__float2bfloat16_rn(v.z));
            float hw = __bfloat162float(__float2bfloat16_rn(v.w));
            uint32_t* p = sa + row * LPITCH + c4 * 2;
            p[0] = pack_bf16(hx, hy);
            p[1] = pack_bf16(hz, hw);
            p[16] = pack_bf16(v.x - hx, v.y - hy);
            p[17] = pack_bf16(v.z - hz, v.w - hw);
        }
#pragma unroll
        for (int i = 0; i < 4; i++) {
            int row = r0g + i * 32;
            float4 v = bReg[i];
            float hx = __bfloat162float(__float2bfloat16_rn(v.x));
            float hy = __bfloat162float(__float2bfloat16_rn(v.y));
            float hz = __bfloat162float(__float2bfloat16_rn(v.z));
            float hw = __bfloat162float(__float2bfloat16_rn(v.w));
            uint32_t* p = sb + row * LPITCH + c4 * 2;
            p[0] = pack_bf16(hx, hy);
            p[1] = pack_bf16(hz, hw);
            p[16] = pack_bf16(v.x - hx, v.y - hy);
            p[17] = pack_bf16(v.z - hz, v.w - hw);
        }
    };

    const uint32_t a_off = (uint32_t)(warp_m * 32 + (lane & 15)) * ROWB + ((lane >> 4) * 16);
    const uint32_t b_off = (uint32_t)(warp_n * 32 + ((lane >> 4) & 1) * 8 + (lane & 7)) * ROWB
                         + (((lane >> 3) & 1) * 16);

    float acc[2][4][4];
#pragma unroll
    for (int i = 0; i < 2; i++)
#pragma unroll
        for (int j = 0; j < 4; j++)
#pragma unroll
            for (int e = 0; e < 4; e++) acc[i][j][e] = 0.f;

    const int KT = K / BKF;
    load_global(0);
    store_stage(0);
    __syncthreads();

    for (int kt = 0; kt < KT; kt++) {
        if (kt + 1 < KT) load_global(kt + 1);
        const uint32_t Ab = sbase + (kt & 1) * STAGE_B;
        const uint32_t Bb = Ab + A_TILE_B;
        // products: hi*hi (ks 0,1) ; lo*hi (ks 2,3) ; hi*lo (ks 4,5)
#pragma unroll
        for (int ks = 0; ks < 6; ks++) {
            const int kk = ks & 1;
            const int segA = (ks == 2 || ks == 3) ? 1 : 0;
            const int segB = (ks >= 4) ? 1 : 0;
            const uint32_t ao = Ab + a_off + segA * 64 + kk * 32;
            const uint32_t bo = Bb + b_off + segB * 64 + kk * 32;
            uint32_t a[2][4];
#pragma unroll
            for (int mt = 0; mt < 2; mt++)
                LDSM_X4(a[mt][0], a[mt][1], a[mt][2], a[mt][3], ao + mt * 16 * ROWB);
            uint32_t b[2][4];
#pragma unroll
            for (int p = 0; p < 2; p++)
                LDSM_X4(b[p][0], b[p][1], b[p][2], b[p][3], bo + p * 16 * ROWB);
#pragma unroll
            for (int mt = 0; mt < 2; mt++) {
                MMA_BF16(acc[mt][0], a[mt], b[0][0], b[0][1]);
                MMA_BF16(acc[mt][1], a[mt], b[0][2], b[0][3]);
                MMA_BF16(acc[mt][2], a[mt], b[1][0], b[1][1]);
                MMA_BF16(acc[mt][3], a[mt], b[1][2], b[1][3]);
            }
        }
        if (kt + 1 < KT) store_stage((kt + 1) & 1);
        __syncthreads();
    }

    // ---- epilogue ----
    const int er = bm + warp_m * 32 + (lane >> 2);
    const int ec = bn + warp_n * 32 + (lane & 3) * 2;
#pragma unroll
    for (int mt = 0; mt < 2; mt++) {
#pragma unroll
        for (int nt = 0; nt < 4; nt++) {
            int gc = ec + nt * 8;
            if (gc >= N) continue;
            float b0 = 0.f, b1 = 0.f;
            if (bias) {
                if (ACT == ACT_DELTABC) {
                    if (gc < 512)     b0 = bias[gc];
                    if (gc + 1 < 512) b1 = bias[gc + 1];
                } else {
                    b0 = bias[gc]; b1 = bias[gc + 1];
                }
            }
#pragma unroll
            for (int h = 0; h < 2; h++) {
                int gr = er + mt * 16 + h * 8;
                if (gr >= M) continue;
                float v0 = acc[mt][nt][h * 2 + 0];
                float v1 = acc[mt][nt][h * 2 + 1];
                if (ACT == ACT_NONE) {
                    v0 += b0; v1 += b1;
                    *reinterpret_cast<float2*>(&C[(size_t)gr * ldc + gc]) =
                        make_float2(v0, v1);
                } else if (ACT == ACT_DUP) {
                    v0 += b0; v1 += b1;
                    float2 o = make_float2(v0, v1);
                    size_t ix = (size_t)gr * ldc + gc;
                    *reinterpret_cast<float2*>(&C[ix]) = o;
                    *reinterpret_cast<float2*>(const_cast<float*>(&e2[ix])) = o;
                } else if (ACT == ACT_RELU) {
                    v0 = fmaxf(v0 + b0, 0.f); v1 = fmaxf(v1 + b1, 0.f);
                    *reinterpret_cast<float2*>(&C[(size_t)gr * ldc + gc]) =
                        make_float2(v0, v1);
                } else if (ACT == ACT_DELTABC) {
                    float* bco = const_cast<float*>(e1) + blockIdx.z * 32;
                    if (gc < 512) {
                        v0 += b0; v1 += b1;
                        v0 = fmaxf(v0, 0.f) + log1pf(__expf(-fabsf(v0)));
                        v1 = fmaxf(v1, 0.f) + log1pf(__expf(-fabsf(v1)));
                        C[(size_t)gr * 2048 + 2 * gc]     = v0;
                        C[(size_t)gr * 2048 + 2 * gc + 2] = v1;
                    } else if (gc < 528) {
                        int s = gc - 512;
                        bco[(size_t)gr * 64 + 2 * s]     = v0;
                        bco[(size_t)gr * 64 + 2 * s + 2] = v1;
                    } else if (gc < 544) {
                        int s = gc - 528;
                        bco[(size_t)gr * 64 + 2 * s + 1] = v0;
                        bco[(size_t)gr * 64 + 2 * s + 3] = v1;
                    }
                } else if (ACT == ACT_GATE) {
                    size_t ix = (size_t)gr * ldc + gc;
                    float s0 = 1.f / (1.f + __expf(-(v0 + b0)));
                    float s1 = 1.f / (1.f + __expf(-(v1 + b1)));
                    v0 = e1[ix] + s0 * e2[ix];
                    v1 = e1[ix + 1] + s1 * e2[ix + 1];
                    *reinterpret_cast<float2*>(&C[ix]) = make_float2(v0, v1);
                }
            }
        }
    }
}

// ================= small kernels ==========================================
__global__ void stats_kernel(const float* __restrict__ x_enc,
                             float* __restrict__ means, float* __restrict__ stds)
{
    int idx = blockIdx.x * blockDim.x + threadIdx.x;
    if (idx >= BATCH * NVARS) return;
    int b = idx / NVARS, n = idx - b * NVARS;
    float s = 0.f, sq = 0.f;
    for (int t = 0; t < SEQ; t++) {
        float v = x_enc[((size_t)b * SEQ + t) * NVARS + n];
        s += v; sq += v * v;
    }
    float m = s * (1.f / SEQ);
    float var = sq * (1.f / SEQ) - m * m;
    means[idx] = m;
    stds[idx] = sqrtf(var + 1e-5f);
}

__global__ void tok_kernel(const float* __restrict__ x_enc,
                           const float* __restrict__ x_mark,
                           const float* __restrict__ means,
                           const float* __restrict__ stds,
                           float* __restrict__ tok)
{
    int idx = blockIdx.x * blockDim.x + threadIdx.x;
    if (idx >= TTOK * SEQ) return;
    int sIdx = idx % SEQ;
    int t = idx / SEQ;
    int b = t / LTOK, v = t - b * LTOK;
    float val;
    if (v < NVARS) {
        val = (x_enc[((size_t)b * SEQ + sIdx) * NVARS + v] - means[b * NVARS + v])
              / stds[b * NVARS + v];
    } else {
        val = x_mark[((size_t)b * SEQ + sIdx) * NMARK + (v - NVARS)];
    }
    tok[idx] = val;
}

// W_comb[w][n][k]
__global__ void wcomb_kernel(const float* __restrict__ dtw,
                             const float* __restrict__ xpw,
                             float* __restrict__ wcomb)
{
    int idx = blockIdx.x * blockDim.x + threadIdx.x;
    if (idx >= 4 * 544 * 512) return;
    int w = idx / (544 * 512);
    int rem = idx - w * 544 * 512;
    int n = rem >> 9;
    int k = rem & 511;
    float v;
    if (n < 512) {
        const float* dr = dtw + ((size_t)w * 512 + n) * 32;
        const float* xr = xpw + (size_t)w * 64 * 512 + k;
        v = 0.f;
#pragma unroll
        for (int r = 0; r < 32; r++) v = fmaf(dr[r], xr[(size_t)r * 512], v);
    } else {
        v = xpw[(size_t)w * 64 * 512 + (size_t)(32 + n - 512) * 512 + k];
    }
    wcomb[idx] = v;
}

// depthwise conv(2) + SiLU, both dirs. xzB: [T,2048] = [xi0|z0|xi1|z1]
__global__ void conv_silu_kernel(const float* __restrict__ xzB,
                                 const float* __restrict__ cw,
                                 const float* __restrict__ cb,
                                 float* __restrict__ xc0, float* __restrict__ xc1,
                                 float* __restrict__ dx)
{
    int idx = blockIdx.x * blockDim.x + threadIdx.x;
    const int n = TTOK * DM;
    if (idx >= 2 * n) return;
    int dir = idx >= n;
    int r = idx - dir * n;
    int d = r & (DM - 1);
    int t = r >> 9;
    int b = t / LTOK, l = t - b * LTOK;
    const float* base = xzB + (size_t)dir * 1024;
    float cur = base[(size_t)t * 2048 + d];
    int ln = dir ? (l + 1) : (l - 1);
    float nb = 0.f;
    if (ln >= 0 && ln < LTOK)
        nb = base[(size_t)(t + (dir ? 1 : -1)) * 2048 + d];
    float w0 = cw[(size_t)dir * DM * 2 + d * 2 + 0];
    float w1 = cw[(size_t)dir * DM * 2 + d * 2 + 1];
    float v = w0 * nb + w1 * cur + cb[dir * DM + d];
    float out = v / (1.f + __expf(-v));
    (dir ? xc1 : xc0)[r] = out;
    dx[(size_t)t * 2048 + dir * 1024 + 2 * d + 1] = out;
}

// ---------------- chunked selective scan -----------------------------------
__global__ void __launch_bounds__(256)
scan_p1(const float* __restrict__ dx, const float* __restrict__ bcb,
        const float* __restrict__ A_log_l,
        float* __restrict__ P, float* __restrict__ H)
{
    int w = blockIdx.x * 8 + (threadIdx.x >> 5);
    int lane = threadIdx.x & 31;
    int ch = w & 31;
    int dblk = (w >> 5) & 15;
    int b = (w >> 9) & 7;
    int dir = w >> 12;
    int d = dblk * 32 + lane;

    float a[DS];
    bool structured = true;
#pragma unroll
    for (int s = 0; s < DS; s++) {
        a[s] = -__expf(A_log_l[((size_t)dir * DM + d) * DS + s]) * 1.44269504f;
        structured = structured &&
            (fabsf(a[s] - a[0] * (s + 1)) <= 1e-4f * fabsf(a[0] * (s + 1)));
    }

    float h[DS], Pr[DS];
#pragma unroll
    for (int s = 0; s < DS; s++) { h[s] = 0.f; Pr[s] = 1.f; }

    int i0 = ch * CHL;
    int nn = LTOK - i0; if (nn > CHL) nn = CHL; if (nn < 0) nn = 0;
    int l0 = dir ? (LTOK - 1 - i0) : i0;
    long t0 = (long)b * LTOK + l0;
    long stp = dir ? -1 : 1;
    const float2* dxp = (const float2*)dx + t0 * 1024 + dir * 512 + d;
    const float2* bp  = (const float2*)bcb + t0 * 32 + dir * 16;
    long sdx = stp * 1024, sbc = stp * 32;

    if (structured) {
        const float a0 = a[0];
        for (int i = 0; i < nn; i++) {
            float2 dv = *dxp;
            float u = dv.x * dv.y;
            float q = exp2f(dv.x * a0);
            float dA = 1.f;
#pragma unroll
            for (int s = 0; s < DS; s++) {
                dA *= q;
                float2 bcv = bp[s];
                Pr[s] *= dA;
                h[s] = fmaf(dA, h[s], bcv.x * u);
            }
            dxp += sdx; bp += sbc;
        }
    } else {
        for (int i = 0; i < nn; i++) {
            float2 dv = *dxp;
            float u = dv.x * dv.y;
#pragma unroll
            for (int s = 0; s < DS; s++) {
                float2 bcv = bp[s];
                float dA = exp2f(dv.x * a[s]);
                Pr[s] *= dA;
                h[s] = fmaf(dA, h[s], bcv.x * u);
            }
            dxp += sdx; bp += sbc;
        }
    }
    float* Po = P + ((size_t)w * 32 + lane) * 16;
    float* Ho = H + ((size_t)w * 32 + lane) * 16;
#pragma unroll
    for (int s = 0; s < DS; s++) { Po[s] = Pr[s]; Ho[s] = h[s]; }
}

__global__ void scan_comb(const float* __restrict__ P,
                          const float* __restrict__ Hl,
                          float* __restrict__ Hin)
{
    int idx = blockIdx.x * blockDim.x + threadIdx.x;
    if (idx >= 2 * BATCH * DM * 16) return;
    int s = idx & 15;
    int lane = (idx >> 4) & 31;
    int dblk = (idx >> 9) & 15;
    int b = (idx >> 13) & 7;
    int dir = idx >> 16;
    size_t w0 = (size_t)dir * 4096 + (size_t)b * 512 + (size_t)dblk * 32;
    float h = 0.f;
#pragma unroll
    for (int ch = 0; ch < NCH; ch++) {
        size_t o = ((w0 + ch) * 32 + lane) * 16 + s;
        Hin[o] = h;
        h = P[o] * h + Hl[o];
    }
}

__global__ void __launch_bounds__(256)
scan_p2(const float* __restrict__ dx, const float* __restrict__ bcb,
        const float* __restrict__ xzB,
        const float* __restrict__ A_log_l,
        const float* __restrict__ Dp_l,
        const float* __restrict__ Hin,
        float* __restrict__ yp0, float* __restrict__ yp1)
{
    int w = blockIdx.x * 8 + (threadIdx.x >> 5);
    int lane = threadIdx.x & 31;
    int ch = w & 31;
    int dblk = (w >> 5) & 15;
    int b = (w >> 9) & 7;
    int dir = w >> 12;
    int d = dblk * 32 + lane;

    float a[DS];
    bool structured = true;
#pragma unroll
    for (int s = 0; s < DS; s++) {
        a[s] = -__expf(A_log_l[((size_t)dir * DM + d) * DS + s]) * 1.44269504f;
        structured = structured &&
            (fabsf(a[s] - a[0] * (s + 1)) <= 1e-4f * fabsf(a[0] * (s + 1)));
    }
    float Dv = Dp_l[dir * DM + d];

    float h[DS];
    const float* Hi = Hin + ((size_t)w * 32 + lane) * 16;
#pragma unroll
    for (int s = 0; s < DS; s++) h[s] = Hi[s];

    int i0 = ch * CHL;
    int nn = LTOK - i0; if (nn > CHL) nn = CHL; if (nn < 0) nn = 0;
    int l0 = dir ? (LTOK - 1 - i0) : i0;
    long t0 = (long)b * LTOK + l0;
    long stp = dir ? -1 : 1;
    const float2* dxp = (const float2*)dx + t0 * 1024 + dir * 512 + d;
    const float2* bp  = (const float2*)bcb + t0 * 32 + dir * 16;
    const float*  zp  = xzB + t0 * 2048 + dir * 1024 + 512 + d;
    float* ypp = (dir ? yp1 : yp0) + t0 * 512 + d;
    long sdx = stp * 1024, sbc = stp * 32, sz = stp * 2048, sy = stp * 512;

    if (structured) {
        const float a0 = a[0];
        for (int i = 0; i < nn; i++) {
            float2 dv = *dxp;
            float u = dv.x * dv.y;
            float q = exp2f(dv.x * a0);
            float dA = 1.f;
            float y0 = 0.f, y1 = 0.f, y2 = 0.f, y3 = 0.f;
#pragma unroll
            for (int s = 0; s < DS; s++) {
                dA *= q;
                float2 bcv = bp[s];
                h[s] = fmaf(dA, h[s], bcv.x * u);
                float t = h[s] * bcv.y;
                if ((s & 3) == 0) y0 += t;
                else if ((s & 3) == 1) y1 += t;
                else if ((s & 3) == 2) y2 += t;
                else y3 += t;
            }
            float y = (y0 + y1) + (y2 + y3);
            float z = *zp;
            float szl = z / (1.f + __expf(-z));
            *ypp = (y + Dv * dv.y) * szl;
            dxp += sdx; bp += sbc; zp += sz; ypp += sy;
        }
    } else {
        for (int i = 0; i < nn; i++) {
            float2 dv = *dxp;
            float u = dv.x * dv.y;
            float y0 = 0.f, y1 = 0.f, y2 = 0.f, y3 = 0.f;
#pragma unroll
            for (int s = 0; s < DS; s++) {
                float2 bcv = bp[s];
                float dA = exp2f(dv.x * a[s]);
                h[s] = fmaf(dA, h[s], bcv.x * u);
                float t = h[s] * bcv.y;
                if ((s & 3) == 0) y0 += t;
                else if ((s & 3) == 1) y1 += t;
                else if ((s & 3) == 2) y2 += t;
                else y3 += t;
            }
            float y = (y0 + y1) + (y2 + y3);
            float z = *zp;
            float szl = z / (1.f + __expf(-z));
            *ypp = (y + Dv * dv.y) * szl;
            dxp += sdx; bp += sbc; zp += sz; ypp += sy;
        }
    }
}

__global__ void ln_kernel(const float* __restrict__ i1,
                          const float* __restrict__ i2,
                          const float* __restrict__ i3,
                          const float* __restrict__ g,
                          const float* __restrict__ bta,
                          float* __restrict__ out)
{
    int row = blockIdx.x * (blockDim.x >> 5) + (threadIdx.x >> 5);
    int lane = threadIdx.x & 31;
    if (row >= TTOK) return;
    size_t rb = (size_t)row * DM;
    float vals[16];
    float s = 0.f, sq = 0.f;
#pragma unroll
    for (int i = 0; i < 16; i++) {
        int c = lane + i * 32;
        float v = i1[rb + c];
        if (i2) v += i2[rb + c];
        if (i3) v += i3[rb + c];
        vals[i] = v; s += v; sq += v * v;
    }
#pragma unroll
    for (int o = 16; o; o >>= 1) {
        s  += __shfl_xor_sync(0xffffffffu, s, o);
        sq += __shfl_xor_sync(0xffffffffu, sq, o);
    }
    float m = s * (1.f / DM);
    float var = sq * (1.f / DM) - m * m;
    float r = rsqrtf(var + 1e-5f);
#pragma unroll
    for (int i = 0; i < 16; i++) {
        int c = lane + i * 32;
        out[rb + c] = (vals[i] - m) * r * g[c] + bta[c];
    }
}

__global__ void out_kernel(const float* __restrict__ dec,
                           const float* __restrict__ means,
                           const float* __restrict__ stds,
                           float* __restrict__ out)
{
    int idx = blockIdx.x * blockDim.x + threadIdx.x;
    if (idx >= BATCH * PRED * NVARS) return;
    int b = idx / (PRED * NVARS);
    int rem = idx - b * (PRED * NVARS);
    int p = rem / NVARS;
    int n = rem - p * NVARS;
    float v = dec[((size_t)b * LTOK + n) * PRED + p];
    out[idx] = v * stds[b * NVARS + n] + means[b * NVARS + n];
}

// ================= host orchestration ======================================
template <int ACT>
static void launch_mma(const float* A, int lda, const float* W, const float* bias,
                       float* C, int ldc, int M, int N, int K,
                       const float* e1 = nullptr, const float* e2 = nullptr,
                       int Z = 1, size_t zsA = 0, size_t zsW = 0,
                       size_t zsC = 0, size_t zsBias = 0)
{
    dim3 grid(CDIV(N, BN), CDIV(M, BM), Z);
    mma_gemm<ACT><<<grid, 256, SMEM_GEMM>>>(A, lda, W, bias, C, ldc, M, N, K,
                                            e1, e2, zsA, zsW, zsC, zsBias);
}

extern "C" void kernel_launch(void* const* d_in, const int* in_sizes, int n_in,
                              void* d_out, int out_size)
{
    const float* x_enc    = (const float*)d_in[0];
    const float* x_mark   = (const float*)d_in[1];
    const float* emb_w    = (const float*)d_in[4];
    const float* emb_b    = (const float*)d_in[5];
    const float* in_proj  = (const float*)d_in[6];
    const float* conv_w   = (const float*)d_in[7];
    const float* conv_b   = (const float*)d_in[8];
    const float* x_proj   = (const float*)d_in[9];
    const float* dt_w     = (const float*)d_in[10];
    const float* dt_b     = (const float*)d_in[11];
    const float* A_log    = (const float*)d_in[12];
    const float* D_param  = (const float*)d_in[13];
    const float* out_w    = (const float*)d_in[14];
    const float* ffn_w1   = (const float*)d_in[15];
    const float* ffn_b1   = (const float*)d_in[16];
    const float* ffn_w2   = (const float*)d_in[17];
    const float* ffn_b2   = (const float*)d_in[18];
    const float* ln1_g    = (const float*)d_in[19];
    const float* ln1_b    = (const float*)d_in[20];
    const float* ln2_g    = (const float*)d_in[21];
    const float* ln2_b    = (const float*)d_in[22];
    const float* fin_g    = (const float*)d_in[23];
    const float* fin_b    = (const float*)d_in[24];
    const float* gate_w   = (const float*)d_in[25];
    const float* gate_b   = (const float*)d_in[26];
    const float* proj_w   = (const float*)d_in[27];
    const float* proj_b   = (const float*)d_in[28];

    cudaFuncSetAttribute(mma_gemm<ACT_NONE>,    cudaFuncAttributeMaxDynamicSharedMemorySize, SMEM_GEMM);
    cudaFuncSetAttribute(mma_gemm<ACT_RELU>,    cudaFuncAttributeMaxDynamicSharedMemorySize, SMEM_GEMM);
    cudaFuncSetAttribute(mma_gemm<ACT_DELTABC>, cudaFuncAttributeMaxDynamicSharedMemorySize, SMEM_GEMM);
    cudaFuncSetAttribute(mma_gemm<ACT_GATE>,    cudaFuncAttributeMaxDynamicSharedMemorySize, SMEM_GEMM);
    cudaFuncSetAttribute(mma_gemm<ACT_DUP>,     cudaFuncAttributeMaxDynamicSharedMemorySize, SMEM_GEMM);

    float* S = nullptr;
    cudaGetSymbolAddress((void**)&S, g_scratch);

    float* tok   = S + OFF_TOK;
    float* dec   = S + OFF_DEC;
    float* enc   = S + OFF_ENC;
    float* raw   = S + OFF_RAW;
    float* xzB   = S + OFF_XZB;
    float* xcb[2] = { S + OFF_XC0,  S + OFF_XC1 };
    float* dx    = S + OFF_DX;
    float* bcb   = S + OFF_BC;
    float* yp[2]  = { S + OFF_YP0,  S + OFF_YP1 };
    float* mo[2]  = { S + OFF_MO0,  S + OFF_MO1 };
    float* t1    = S + OFF_T1;
    float* t2    = S + OFF_T2;
    float* t3    = S + OFF_T3;
    float* wcomb = S + OFF_WCOMB;
    float* means = S + OFF_MEAN;
    float* stds  = S + OFF_STD;
    float* Pbuf  = S + OFF_P;
    float* Hlbuf = S + OFF_HL;
    float* Hibuf = S + OFF_HI;

    stats_kernel<<<CDIV(BATCH * NVARS, 256), 256>>>(x_enc, means, stds);
    tok_kernel<<<CDIV(TTOK * SEQ, 256), 256>>>(x_enc, x_mark, means, stds, tok);
    wcomb_kernel<<<CDIV(4 * 544 * 512, 256), 256>>>(dt_w, x_proj, wcomb);

    // embedding GEMM -> enc (+ duplicate into raw)
    launch_mma<ACT_DUP>(tok, SEQ, emb_w, emb_b, enc, DM, TTOK, DM, SEQ,
                        nullptr, raw);

    for (int l = 0; l < NL; l++) {
        // merged fwd+rev in_proj: N=2048
        launch_mma<ACT_NONE>(enc, DM, in_proj + (size_t)l * 2 * 2 * DM * DM,
                             nullptr, xzB, 4 * DM, TTOK, 4 * DM, DM);
        conv_silu_kernel<<<CDIV(2 * TTOK * DM, 256), 256>>>(
            xzB, conv_w + (size_t)l * 2 * DM * 2, conv_b + (size_t)l * 2 * DM,
            xcb[0], xcb[1], dx);

        // fused delta(softplus)+B+C GEMM, both dirs (z=2) -> dx / bcb
        launch_mma<ACT_DELTABC>(xcb[0], DM, wcomb + (size_t)l * 2 * 544 * 512,
                                dt_b + (size_t)l * 2 * DM, dx, 2048,
                                TTOK, 544, DM, bcb, nullptr,
                                2, (size_t)TTOK * DM, (size_t)544 * 512,
                                1024, DM);

        // chunked scan
        scan_p1<<<NWARP / 8, 256>>>(dx, bcb,
                                    A_log + (size_t)l * 2 * DM * DS,
                                    Pbuf, Hlbuf);
        scan_comb<<<CDIV(2 * BATCH * DM * 16, 256), 256>>>(Pbuf, Hlbuf, Hibuf);
        scan_p2<<<NWARP / 8, 256>>>(dx, bcb, xzB,
                                    A_log + (size_t)l * 2 * DM * DS,
                                    D_param + (size_t)l * 2 * DM,
                                    Hibuf, yp[0], yp[1]);

        // out projection, both dirs (z=2)
        launch_mma<ACT_NONE>(yp[0], DM, out_w + (size_t)l * 2 * DM * DM,
                             nullptr, mo[0], DM, TTOK, DM, DM, nullptr, nullptr,
                             2, (size_t)TTOK * DM, (size_t)DM * DM,
                             (size_t)TTOK * DM, 0);

        ln_kernel<<<CDIV(TTOK, 8), 256>>>(enc, mo[0], mo[1],
                                          ln1_g + l * DM, ln1_b + l * DM, t1);
        launch_mma<ACT_RELU>(t1, DM, ffn_w1 + (size_t)l * DFF * DM,
                             ffn_b1 + l * DFF, t2, DFF, TTOK, DFF, DM);
        launch_mma<ACT_NONE>(t2, DFF, ffn_w2 + (size_t)l * DM * DFF,
                             ffn_b2 + l * DM, t3, DM, TTOK, DM, DFF);
        ln_kernel<<<CDIV(TTOK, 8), 256>>>(t1, t3, nullptr,
                                          ln2_g + l * DM, ln2_b + l * DM, enc);
    }

    ln_kernel<<<CDIV(TTOK, 8), 256>>>(enc, nullptr, nullptr, fin_g, fin_b, t2);
    launch_mma<ACT_GATE>(raw, DM, gate_w, gate_b, t1, DM, TTOK, DM, DM, t2, raw);
    launch_mma<ACT_NONE>(t1, DM, proj_w, proj_b, dec, PRED, TTOK, PRED, DM);
    out_kernel<<<CDIV(BATCH * PRED * NVARS, 256), 256>>>(dec, means, stds,
                                                         (float*)d_out);
}